// round 3
// baseline (speedup 1.0000x reference)
#include <cuda_runtime.h>
#include <math.h>

#define MTOT 32768
#define CDIM 1024
#define HDIM 4096
#define EDIM 8

// Scratch (device globals — no allocation allowed in kernel_launch)
__device__ float g_h[(size_t)MTOT * HDIM];   // 512 MB: GELU(x@W1+b1)
__device__ float g_q[(size_t)MTOT * CDIM];   // 128 MB: h@W2+b2

#define BM 128
#define BN 128
#define BK 16

__device__ __forceinline__ float gelu_exact(float v) {
    return 0.5f * v * (1.0f + erff(v * 0.70710678118654752440f));
}

// C[M,N] = A[M,K] @ B[K,N] + bias[N], optional exact-GELU epilogue.
// M % 128 == 0, N % 128 == 0, K % 16 == 0 (all true for our shapes).
template<int GELU_EPI>
__global__ void __launch_bounds__(256)
sgemm_bias(const float* __restrict__ A, const float* __restrict__ B,
           const float* __restrict__ bias, float* __restrict__ C,
           int M, int N, int Kd)
{
    __shared__ __align__(16) float As[2][BK][BM + 4];
    __shared__ __align__(16) float Bs[2][BK][BN];

    const int tid = threadIdx.x;
    const int tx = tid & 15;        // 0..15 -> output col block
    const int ty = tid >> 4;        // 0..15 -> output row block
    const int bx = blockIdx.x, by = blockIdx.y;

    const float* Abase = A + (size_t)by * BM * Kd;
    const float* Bbase = B + (size_t)bx * BN;

    float acc[8][8];
#pragma unroll
    for (int i = 0; i < 8; i++)
#pragma unroll
        for (int j = 0; j < 8; j++) acc[i][j] = 0.f;

    // A tile: 128x16 floats = 512 float4; 2 per thread. pos -> (row, c4)
    const int aRow0 = tid >> 2,        aC40 = (tid & 3) * 4;
    const int aRow1 = (tid + 256) >> 2, aC41 = ((tid + 256) & 3) * 4;
    // B tile: 16x128 floats = 512 float4; 2 per thread. pos -> (row, col)
    const int bRow0 = tid >> 5,        bCol0 = (tid & 31) * 4;
    const int bRow1 = (tid + 256) >> 5, bCol1 = ((tid + 256) & 31) * 4;

    float4 aP0, aP1, bP0, bP1;

    // Prologue: load tile 0
    aP0 = *(const float4*)(Abase + (size_t)aRow0 * Kd + aC40);
    aP1 = *(const float4*)(Abase + (size_t)aRow1 * Kd + aC41);
    bP0 = *(const float4*)(Bbase + (size_t)bRow0 * N + bCol0);
    bP1 = *(const float4*)(Bbase + (size_t)bRow1 * N + bCol1);

    As[0][aC40 + 0][aRow0] = aP0.x; As[0][aC40 + 1][aRow0] = aP0.y;
    As[0][aC40 + 2][aRow0] = aP0.z; As[0][aC40 + 3][aRow0] = aP0.w;
    As[0][aC41 + 0][aRow1] = aP1.x; As[0][aC41 + 1][aRow1] = aP1.y;
    As[0][aC41 + 2][aRow1] = aP1.z; As[0][aC41 + 3][aRow1] = aP1.w;
    *(float4*)&Bs[0][bRow0][bCol0] = bP0;
    *(float4*)&Bs[0][bRow1][bCol1] = bP1;
    __syncthreads();

    const int nTiles = Kd / BK;
    for (int t = 0; t < nTiles; t++) {
        const int cur = t & 1;
        if (t + 1 < nTiles) {
            const float* An = Abase + (size_t)(t + 1) * BK;
            const float* Bn = Bbase + (size_t)(t + 1) * BK * N;
            aP0 = *(const float4*)(An + (size_t)aRow0 * Kd + aC40);
            aP1 = *(const float4*)(An + (size_t)aRow1 * Kd + aC41);
            bP0 = *(const float4*)(Bn + (size_t)bRow0 * N + bCol0);
            bP1 = *(const float4*)(Bn + (size_t)bRow1 * N + bCol1);
        }
#pragma unroll
        for (int kk = 0; kk < BK; kk++) {
            float a[8], b[8];
            float4 t0 = *(const float4*)&As[cur][kk][ty * 8];
            float4 t1 = *(const float4*)&As[cur][kk][ty * 8 + 4];
            float4 t2 = *(const float4*)&Bs[cur][kk][tx * 8];
            float4 t3 = *(const float4*)&Bs[cur][kk][tx * 8 + 4];
            a[0] = t0.x; a[1] = t0.y; a[2] = t0.z; a[3] = t0.w;
            a[4] = t1.x; a[5] = t1.y; a[6] = t1.z; a[7] = t1.w;
            b[0] = t2.x; b[1] = t2.y; b[2] = t2.z; b[3] = t2.w;
            b[4] = t3.x; b[5] = t3.y; b[6] = t3.z; b[7] = t3.w;
#pragma unroll
            for (int i = 0; i < 8; i++)
#pragma unroll
                for (int j = 0; j < 8; j++)
                    acc[i][j] += a[i] * b[j];
        }
        if (t + 1 < nTiles) {
            const int nxt = cur ^ 1;
            As[nxt][aC40 + 0][aRow0] = aP0.x; As[nxt][aC40 + 1][aRow0] = aP0.y;
            As[nxt][aC40 + 2][aRow0] = aP0.z; As[nxt][aC40 + 3][aRow0] = aP0.w;
            As[nxt][aC41 + 0][aRow1] = aP1.x; As[nxt][aC41 + 1][aRow1] = aP1.y;
            As[nxt][aC41 + 2][aRow1] = aP1.z; As[nxt][aC41 + 3][aRow1] = aP1.w;
            *(float4*)&Bs[nxt][bRow0][bCol0] = bP0;
            *(float4*)&Bs[nxt][bRow1][bCol1] = bP1;
        }
        __syncthreads();
    }

    // Epilogue: bias (+ exact GELU), float4 stores
    const int row0 = by * BM + ty * 8;
    const int col0 = bx * BN + tx * 8;
    float bv[8];
#pragma unroll
    for (int j = 0; j < 8; j++) bv[j] = bias[col0 + j];
#pragma unroll
    for (int i = 0; i < 8; i++) {
        float v[8];
#pragma unroll
        for (int j = 0; j < 8; j++) {
            float val = acc[i][j] + bv[j];
            if (GELU_EPI) val = gelu_exact(val);
            v[j] = val;
        }
        float* Cp = C + (size_t)(row0 + i) * N + col0;
        *(float4*)Cp       = make_float4(v[0], v[1], v[2], v[3]);
        *(float4*)(Cp + 4) = make_float4(v[4], v[5], v[6], v[7]);
    }
}

// One warp per token: scores = q . type_queries[e], gate = sigmoid(x . noise_w + nb),
// noisy = scores + temp*noise*gate, top-2 (ties -> lower index, matching lax.top_k),
// sparse softmax over the 2 selected experts (others exactly 0).
__global__ void __launch_bounds__(256)
route_kernel(const float* __restrict__ q, const float* __restrict__ x,
             const float* __restrict__ noise, const float* __restrict__ tq,
             const float* __restrict__ nw, const float* __restrict__ nb,
             const float* __restrict__ temp_p,
             float* __restrict__ out_router, float* __restrict__ out_idx, int M)
{
    __shared__ float tqs[EDIM][CDIM];   // 32 KB
    __shared__ float nws[CDIM];         // 4 KB
    for (int i = threadIdx.x; i < EDIM * CDIM; i += blockDim.x)
        ((float*)tqs)[i] = tq[i];
    for (int i = threadIdx.x; i < CDIM; i += blockDim.x)
        nws[i] = nw[i];
    __syncthreads();

    const int lane = threadIdx.x & 31;
    const int warp = threadIdx.x >> 5;
    const float temp = *temp_p;
    const float nbv  = *nb;

    for (int t = blockIdx.x * 8 + warp; t < M; t += gridDim.x * 8) {
        const float* qr = q + (size_t)t * CDIM;
        const float* xr = x + (size_t)t * CDIM;
        float acc[EDIM];
        float accg = 0.f;
#pragma unroll
        for (int e = 0; e < EDIM; e++) acc[e] = 0.f;

        for (int j = lane; j < CDIM; j += 32) {
            float qv = qr[j];
            float xv = xr[j];
            accg += xv * nws[j];
#pragma unroll
            for (int e = 0; e < EDIM; e++) acc[e] += qv * tqs[e][j];
        }
#pragma unroll
        for (int off = 16; off >= 1; off >>= 1) {
#pragma unroll
            for (int e = 0; e < EDIM; e++)
                acc[e] += __shfl_xor_sync(0xffffffffu, acc[e], off);
            accg += __shfl_xor_sync(0xffffffffu, accg, off);
        }

        float gate = 1.f / (1.f + expf(-(accg + nbv)));
        float noisy[EDIM];
#pragma unroll
        for (int e = 0; e < EDIM; e++)
            noisy[e] = acc[e] + temp * noise[(size_t)t * EDIM + e] * gate;

        // top-2, ties broken toward lower index (strict > keeps first occurrence)
        int i0 = 0; float v0 = noisy[0];
#pragma unroll
        for (int e = 1; e < EDIM; e++)
            if (noisy[e] > v0) { v0 = noisy[e]; i0 = e; }
        int i1 = -1; float v1 = -INFINITY;
#pragma unroll
        for (int e = 0; e < EDIM; e++)
            if (e != i0 && noisy[e] > v1) { v1 = noisy[e]; i1 = e; }

        float inv = 1.f / (temp + 1e-6f);
        float e1 = expf((v1 - v0) * inv);   // exp of max-shifted value, like jax softmax
        float denom = 1.f + e1;
        float p0 = 1.f / denom;
        float p1 = e1 / denom;

        if (lane < EDIM) {
            float pv = (lane == i0) ? p0 : ((lane == i1) ? p1 : 0.f);
            out_router[(size_t)t * EDIM + lane] = pv;
        }
        if (out_idx != nullptr && lane == 0) {
            out_idx[(size_t)t * 2 + 0] = (float)i0;
            out_idx[(size_t)t * 2 + 1] = (float)i1;
        }
    }
}

extern "C" void kernel_launch(void* const* d_in, const int* in_sizes, int n_in,
                              void* d_out, int out_size)
{
    const float* x     = (const float*)d_in[0];  // [B,T,C]
    const float* noise = (const float*)d_in[1];  // [B,T,E]
    const float* W1    = (const float*)d_in[2];  // [C,H]
    const float* b1    = (const float*)d_in[3];  // [H]
    const float* W2    = (const float*)d_in[4];  // [H,C]
    const float* b2    = (const float*)d_in[5];  // [C]
    const float* tq    = (const float*)d_in[6];  // [E,C]
    const float* nw    = (const float*)d_in[7];  // [C,1]
    const float* nb    = (const float*)d_in[8];  // [1]
    const float* temp  = (const float*)d_in[9];  // scalar

    const int M = in_sizes[0] / CDIM;            // B*T = 32768

    float *hbuf, *qbuf;
    cudaGetSymbolAddress((void**)&hbuf, g_h);
    cudaGetSymbolAddress((void**)&qbuf, g_q);

    dim3 blk(256);
    // GEMM1: h = GELU(x @ W1 + b1)   [M,H]
    dim3 g1(HDIM / BN, M / BM);
    sgemm_bias<1><<<g1, blk>>>(x, W1, b1, hbuf, M, HDIM, CDIM);
    // GEMM2: q = h @ W2 + b2         [M,C]
    dim3 g2(CDIM / BN, M / BM);
    sgemm_bias<0><<<g2, blk>>>(hbuf, W2, b2, qbuf, M, CDIM, HDIM);

    // Output: router_output [M,E] then (if space) topk_idx [M,K] as float
    float* out = (float*)d_out;
    float* out_router = out;
    float* out_idx = nullptr;
    if (out_size >= M * EDIM + M * 2)
        out_idx = out + (size_t)M * EDIM;

    route_kernel<<<M / 8, 256>>>(qbuf, x, noise, tq, nw, nb, temp,
                                 out_router, out_idx, M);
}

// round 6
// speedup vs baseline: 2.4836x; 2.4836x over previous
#include <cuda_runtime.h>
#include <cuda_bf16.h>
#include <math.h>
#include <stdint.h>

#define MTOT 32768
#define CDIM 1024
#define HDIM 4096
#define EDIM 8

// ---- GEMM tiling: 128x128 CTA tile, BK=32, 8 warps of 64x32, 3 cp.async stages ----
#define ROWB   80                 // bytes per smem row: 32 bf16 (64B) + 16B pad -> conflict-free ldmatrix
#define OFF_AH 0
#define OFF_AL 10240
#define OFF_BH 20480
#define OFF_BL 30720
#define STAGE  40960
#define SMEM_TOT (3 * STAGE)      // 122880 bytes

// ---------------- device globals (no runtime allocation allowed) ----------------
__device__ __nv_bfloat16 g_xh[(size_t)MTOT*CDIM], g_xl[(size_t)MTOT*CDIM];   // x split
__device__ __nv_bfloat16 g_w1h[(size_t)HDIM*CDIM], g_w1l[(size_t)HDIM*CDIM]; // W1^T split [N][K]
__device__ __nv_bfloat16 g_w2h[(size_t)CDIM*HDIM], g_w2l[(size_t)CDIM*HDIM]; // W2^T split [N][K]
__device__ __nv_bfloat16 g_hh[(size_t)MTOT*HDIM], g_hl[(size_t)MTOT*HDIM];   // h split
__device__ float g_q[(size_t)MTOT*CDIM];

// ---------------- PTX helpers (base sm_100-compatible PTX only!) ----------------
__device__ __forceinline__ uint32_t smem_u32(const void* p) {
    uint32_t a;
    asm("{ .reg .u64 t; cvta.to.shared.u64 t, %1; cvt.u32.u64 %0, t; }" : "=r"(a) : "l"(p));
    return a;
}
__device__ __forceinline__ void cpa16(uint32_t d, const void* s) {
    asm volatile("cp.async.cg.shared.global [%0], [%1], 16;" :: "r"(d), "l"(s));
}
#define CP_COMMIT() asm volatile("cp.async.commit_group;" ::: "memory")
#define CP_WAIT1()  asm volatile("cp.async.wait_group 1;" ::: "memory")

__device__ __forceinline__ void ldsm4(uint32_t* r, uint32_t a) {
    asm volatile("ldmatrix.sync.aligned.m8n8.x4.shared.b16 {%0,%1,%2,%3}, [%4];"
        : "=r"(r[0]), "=r"(r[1]), "=r"(r[2]), "=r"(r[3]) : "r"(a));
}
__device__ __forceinline__ void mma16816(float* c, const uint32_t* a, const uint32_t* b) {
    asm volatile("mma.sync.aligned.m16n8k16.row.col.f32.bf16.bf16.f32 "
        "{%0,%1,%2,%3}, {%4,%5,%6,%7}, {%8,%9}, {%0,%1,%2,%3};"
        : "+f"(c[0]), "+f"(c[1]), "+f"(c[2]), "+f"(c[3])
        : "r"(a[0]), "r"(a[1]), "r"(a[2]), "r"(a[3]), "r"(b[0]), "r"(b[1]));
}

__device__ __forceinline__ float gelu_exact(float v) {
    return 0.5f * v * (1.0f + erff(v * 0.70710678118654752440f));
}

// ---------------- prep kernels ----------------
__global__ void __launch_bounds__(256)
split_x_kernel(const float* __restrict__ in, __nv_bfloat16* __restrict__ hi,
               __nv_bfloat16* __restrict__ lo, int n4)
{
    int i = blockIdx.x * blockDim.x + threadIdx.x;
    if (i >= n4) return;
    float4 v = ((const float4*)in)[i];
    __nv_bfloat16 h0 = __float2bfloat16(v.x), h1 = __float2bfloat16(v.y);
    __nv_bfloat16 h2 = __float2bfloat16(v.z), h3 = __float2bfloat16(v.w);
    __nv_bfloat16 l0 = __float2bfloat16(v.x - __bfloat162float(h0));
    __nv_bfloat16 l1 = __float2bfloat16(v.y - __bfloat162float(h1));
    __nv_bfloat16 l2 = __float2bfloat16(v.z - __bfloat162float(h2));
    __nv_bfloat16 l3 = __float2bfloat16(v.w - __bfloat162float(h3));
    uint2 hh, ll;
    hh.x = (uint32_t)__bfloat16_as_ushort(h0) | ((uint32_t)__bfloat16_as_ushort(h1) << 16);
    hh.y = (uint32_t)__bfloat16_as_ushort(h2) | ((uint32_t)__bfloat16_as_ushort(h3) << 16);
    ll.x = (uint32_t)__bfloat16_as_ushort(l0) | ((uint32_t)__bfloat16_as_ushort(l1) << 16);
    ll.y = (uint32_t)__bfloat16_as_ushort(l2) | ((uint32_t)__bfloat16_as_ushort(l3) << 16);
    ((uint2*)hi)[i] = hh;
    ((uint2*)lo)[i] = ll;
}

// W [K][N] row-major -> T [N][K] bf16 hi/lo
__global__ void __launch_bounds__(1024)
tsplit_kernel(const float* __restrict__ W, __nv_bfloat16* __restrict__ Th,
              __nv_bfloat16* __restrict__ Tl, int K, int N)
{
    __shared__ float t[32][33];
    int n0 = blockIdx.x * 32, k0 = blockIdx.y * 32;
    t[threadIdx.y][threadIdx.x] = W[(size_t)(k0 + threadIdx.y) * N + n0 + threadIdx.x];
    __syncthreads();
    float v = t[threadIdx.x][threadIdx.y];   // = W[k0+tx][n0+ty]
    int n = n0 + threadIdx.y, k = k0 + threadIdx.x;
    __nv_bfloat16 h = __float2bfloat16(v);
    Th[(size_t)n * K + k] = h;
    Tl[(size_t)n * K + k] = __float2bfloat16(v - __bfloat162float(h));
}

// ---------------- stage loader: 4 tiles x 128 rows x 32 bf16, 2 x 16B chunks/thread/tile ----------------
template<int KTOT>
__device__ __forceinline__ void issue_stage(
    const __nv_bfloat16* __restrict__ Ah, const __nv_bfloat16* __restrict__ Al,
    const __nv_bfloat16* __restrict__ Bh, const __nv_bfloat16* __restrict__ Bl,
    uint32_t stage_base, int kblk, int tid)
{
    const size_t kb = (size_t)kblk * 32;
#pragma unroll
    for (int j = 0; j < 2; j++) {
        int idx = tid + j * 256;
        int r = idx >> 2, ch = idx & 3;
        uint32_t so = stage_base + r * ROWB + ch * 16;
        size_t go = (size_t)r * KTOT + kb + ch * 8;
        cpa16(so + OFF_AH, Ah + go);
        cpa16(so + OFF_AL, Al + go);
        cpa16(so + OFF_BH, Bh + go);
        cpa16(so + OFF_BL, Bl + go);
    }
}

// ---------------- mma.sync GEMM: C = A@B^T (+bias, opt GELU-split epilogue) ----------------
// A: [M][KTOT] bf16 hi/lo, B: [NTOT][KTOT] bf16 hi/lo. 3 terms: Ah*Bh + Ah*Bl + Al*Bh.
template<int KTOT, int NOUT, int GELU_EPI>
__global__ void __launch_bounds__(256, 1)
gemm_mma(const __nv_bfloat16* __restrict__ Ah, const __nv_bfloat16* __restrict__ Al,
         const __nv_bfloat16* __restrict__ Bh, const __nv_bfloat16* __restrict__ Bl,
         const float* __restrict__ bias,
         float* __restrict__ Cf, __nv_bfloat16* __restrict__ Ch, __nv_bfloat16* __restrict__ Cl)
{
    extern __shared__ __align__(128) char smem[];
    const uint32_t sb = smem_u32(smem);
    const int tid = threadIdx.x;
    const int wid = tid >> 5, lane = tid & 31;
    const int warp_m = wid >> 2, warp_n = wid & 3;   // 2 x 4 warp grid, 64x32 per warp
    const int bx = blockIdx.x, by = blockIdx.y;
    constexpr int NCH = KTOT / 32;

    const __nv_bfloat16* At_h = Ah + (size_t)(by * 128) * KTOT;
    const __nv_bfloat16* At_l = Al + (size_t)(by * 128) * KTOT;
    const __nv_bfloat16* Bt_h = Bh + (size_t)(bx * 128) * KTOT;
    const __nv_bfloat16* Bt_l = Bl + (size_t)(bx * 128) * KTOT;

    float acc[4][4][4];
#pragma unroll
    for (int i = 0; i < 4; i++)
#pragma unroll
        for (int j = 0; j < 4; j++)
#pragma unroll
            for (int k = 0; k < 4; k++) acc[i][j][k] = 0.f;

    // prologue: stages 0,1
    issue_stage<KTOT>(At_h, At_l, Bt_h, Bt_l, sb + 0 * STAGE, 0, tid);
    CP_COMMIT();
    issue_stage<KTOT>(At_h, At_l, Bt_h, Bt_l, sb + 1 * STAGE, 1, tid);
    CP_COMMIT();
    CP_WAIT1();
    __syncthreads();

    // ldmatrix lane addressing (constant parts)
    const int aRow = warp_m * 64 + (lane & 15);
    const int aCol16 = (lane >> 4) * 16;
    const int bRow = warp_n * 32 + (lane & 7) + ((lane >> 4) << 3);
    const int bCol16 = ((lane >> 3) & 1) * 16;

#pragma unroll 1
    for (int c = 0; c < NCH; c++) {
        const uint32_t st = sb + (c % 3) * STAGE;
        // issue stage c+2 (overwrites buffer consumed at iter c-1; all threads synced since)
        if (c + 2 < NCH)
            issue_stage<KTOT>(At_h, At_l, Bt_h, Bt_l, sb + ((c + 2) % 3) * STAGE, c + 2, tid);
        CP_COMMIT();

#pragma unroll
        for (int ks = 0; ks < 2; ks++) {
            uint32_t ahf[4][4], alf[4][4], bhf[2][4], blf[2][4];
#pragma unroll
            for (int mt = 0; mt < 4; mt++) {
                uint32_t ad = st + OFF_AH + (uint32_t)(aRow + mt * 16) * ROWB + aCol16 + ks * 32;
                ldsm4(ahf[mt], ad);
                ldsm4(alf[mt], ad + (OFF_AL - OFF_AH));
            }
#pragma unroll
            for (int nh = 0; nh < 2; nh++) {
                uint32_t bd = st + OFF_BH + (uint32_t)(bRow + nh * 16) * ROWB + bCol16 + ks * 32;
                ldsm4(bhf[nh], bd);
                ldsm4(blf[nh], bd + (OFF_BL - OFF_BH));
            }
#pragma unroll
            for (int mt = 0; mt < 4; mt++)
#pragma unroll
                for (int nt = 0; nt < 4; nt++) {
                    const uint32_t* bh2 = &bhf[nt >> 1][(nt & 1) * 2];
                    const uint32_t* bl2 = &blf[nt >> 1][(nt & 1) * 2];
                    mma16816(acc[mt][nt], ahf[mt], bh2);
                    mma16816(acc[mt][nt], ahf[mt], bl2);
                    mma16816(acc[mt][nt], alf[mt], bh2);
                }
        }
        CP_WAIT1();
        __syncthreads();
    }

    // epilogue: c-frag (m16n8): c0,c1 -> row lane>>2, cols 2*(lane&3)+{0,1}; c2,c3 -> row+8
#pragma unroll
    for (int mt = 0; mt < 4; mt++) {
        const int row0 = by * 128 + warp_m * 64 + mt * 16 + (lane >> 2);
#pragma unroll
        for (int nt = 0; nt < 4; nt++) {
            const int col = bx * 128 + warp_n * 32 + nt * 8 + (lane & 3) * 2;
            const float bv0 = __ldg(bias + col), bv1 = __ldg(bias + col + 1);
#pragma unroll
            for (int half = 0; half < 2; half++) {
                const int row = row0 + half * 8;
                float v0 = acc[mt][nt][half * 2 + 0] + bv0;
                float v1 = acc[mt][nt][half * 2 + 1] + bv1;
                if (GELU_EPI) {
                    v0 = gelu_exact(v0); v1 = gelu_exact(v1);
                    __nv_bfloat16 h0 = __float2bfloat16(v0), h1 = __float2bfloat16(v1);
                    __nv_bfloat16 l0 = __float2bfloat16(v0 - __bfloat162float(h0));
                    __nv_bfloat16 l1 = __float2bfloat16(v1 - __bfloat162float(h1));
                    uint32_t ph = (uint32_t)__bfloat16_as_ushort(h0) | ((uint32_t)__bfloat16_as_ushort(h1) << 16);
                    uint32_t pl = (uint32_t)__bfloat16_as_ushort(l0) | ((uint32_t)__bfloat16_as_ushort(l1) << 16);
                    *(uint32_t*)(Ch + (size_t)row * NOUT + col) = ph;
                    *(uint32_t*)(Cl + (size_t)row * NOUT + col) = pl;
                } else {
                    *(float2*)(Cf + (size_t)row * NOUT + col) = make_float2(v0, v1);
                }
            }
        }
    }
}

// ---------------- routing tail (unchanged from passing R2 kernel) ----------------
__global__ void __launch_bounds__(256)
route_kernel(const float* __restrict__ q, const float* __restrict__ x,
             const float* __restrict__ noise, const float* __restrict__ tq,
             const float* __restrict__ nw, const float* __restrict__ nb,
             const float* __restrict__ temp_p,
             float* __restrict__ out_router, float* __restrict__ out_idx, int M)
{
    __shared__ float tqs[EDIM][CDIM];
    __shared__ float nws[CDIM];
    for (int i = threadIdx.x; i < EDIM * CDIM; i += blockDim.x)
        ((float*)tqs)[i] = tq[i];
    for (int i = threadIdx.x; i < CDIM; i += blockDim.x)
        nws[i] = nw[i];
    __syncthreads();

    const int lane = threadIdx.x & 31;
    const int warp = threadIdx.x >> 5;
    const float temp = *temp_p;
    const float nbv  = *nb;

    for (int t = blockIdx.x * 8 + warp; t < M; t += gridDim.x * 8) {
        const float* qr = q + (size_t)t * CDIM;
        const float* xr = x + (size_t)t * CDIM;
        float acc[EDIM];
        float accg = 0.f;
#pragma unroll
        for (int e = 0; e < EDIM; e++) acc[e] = 0.f;

        for (int j = lane; j < CDIM; j += 32) {
            float qv = qr[j];
            float xv = xr[j];
            accg += xv * nws[j];
#pragma unroll
            for (int e = 0; e < EDIM; e++) acc[e] += qv * tqs[e][j];
        }
#pragma unroll
        for (int off = 16; off >= 1; off >>= 1) {
#pragma unroll
            for (int e = 0; e < EDIM; e++)
                acc[e] += __shfl_xor_sync(0xffffffffu, acc[e], off);
            accg += __shfl_xor_sync(0xffffffffu, accg, off);
        }

        float gate = 1.f / (1.f + expf(-(accg + nbv)));
        float noisy[EDIM];
#pragma unroll
        for (int e = 0; e < EDIM; e++)
            noisy[e] = acc[e] + temp * noise[(size_t)t * EDIM + e] * gate;

        int i0 = 0; float v0 = noisy[0];
#pragma unroll
        for (int e = 1; e < EDIM; e++)
            if (noisy[e] > v0) { v0 = noisy[e]; i0 = e; }
        int i1 = -1; float v1 = -INFINITY;
#pragma unroll
        for (int e = 0; e < EDIM; e++)
            if (e != i0 && noisy[e] > v1) { v1 = noisy[e]; i1 = e; }

        float inv = 1.f / (temp + 1e-6f);
        float e1 = expf((v1 - v0) * inv);
        float denom = 1.f + e1;
        float p0 = 1.f / denom;
        float p1 = e1 / denom;

        if (lane < EDIM) {
            float pv = (lane == i0) ? p0 : ((lane == i1) ? p1 : 0.f);
            out_router[(size_t)t * EDIM + lane] = pv;
        }
        if (out_idx != nullptr && lane == 0) {
            out_idx[(size_t)t * 2 + 0] = (float)i0;
            out_idx[(size_t)t * 2 + 1] = (float)i1;
        }
    }
}

// ---------------- launch ----------------
extern "C" void kernel_launch(void* const* d_in, const int* in_sizes, int n_in,
                              void* d_out, int out_size)
{
    const float* x     = (const float*)d_in[0];
    const float* noise = (const float*)d_in[1];
    const float* W1    = (const float*)d_in[2];
    const float* b1    = (const float*)d_in[3];
    const float* W2    = (const float*)d_in[4];
    const float* b2    = (const float*)d_in[5];
    const float* tq    = (const float*)d_in[6];
    const float* nw    = (const float*)d_in[7];
    const float* nb    = (const float*)d_in[8];
    const float* temp  = (const float*)d_in[9];

    const int M = in_sizes[0] / CDIM;   // 32768

    __nv_bfloat16 *xh, *xl, *w1h, *w1l, *w2h, *w2l, *hh, *hl;
    float* qbuf;
    cudaGetSymbolAddress((void**)&xh,  g_xh);  cudaGetSymbolAddress((void**)&xl,  g_xl);
    cudaGetSymbolAddress((void**)&w1h, g_w1h); cudaGetSymbolAddress((void**)&w1l, g_w1l);
    cudaGetSymbolAddress((void**)&w2h, g_w2h); cudaGetSymbolAddress((void**)&w2l, g_w2l);
    cudaGetSymbolAddress((void**)&hh,  g_hh);  cudaGetSymbolAddress((void**)&hl,  g_hl);
    cudaGetSymbolAddress((void**)&qbuf, g_q);

    cudaFuncSetAttribute(gemm_mma<CDIM, HDIM, 1>, cudaFuncAttributeMaxDynamicSharedMemorySize, SMEM_TOT);
    cudaFuncSetAttribute(gemm_mma<HDIM, CDIM, 0>, cudaFuncAttributeMaxDynamicSharedMemorySize, SMEM_TOT);

    // prep: split x, transpose+split W1/W2
    int n4 = (M * CDIM) / 4;
    split_x_kernel<<<(n4 + 255) / 256, 256>>>(x, xh, xl, n4);
    tsplit_kernel<<<dim3(HDIM / 32, CDIM / 32), dim3(32, 32)>>>(W1, w1h, w1l, CDIM, HDIM);
    tsplit_kernel<<<dim3(CDIM / 32, HDIM / 32), dim3(32, 32)>>>(W2, w2h, w2l, HDIM, CDIM);

    // GEMM1: h = GELU(x@W1+b1), stored as bf16 split
    gemm_mma<CDIM, HDIM, 1><<<dim3(HDIM / 128, M / 128), 256, SMEM_TOT>>>(
        xh, xl, w1h, w1l, b1, nullptr, hh, hl);
    // GEMM2: q = h@W2+b2, fp32
    gemm_mma<HDIM, CDIM, 0><<<dim3(CDIM / 128, M / 128), 256, SMEM_TOT>>>(
        hh, hl, w2h, w2l, b2, qbuf, nullptr, nullptr);

    float* out = (float*)d_out;
    float* out_router = out;
    float* out_idx = nullptr;
    if (out_size >= M * EDIM + M * 2)
        out_idx = out + (size_t)M * EDIM;

    route_kernel<<<M / 8, 256>>>(qbuf, x, noise, tq, nw, nb, temp,
                                 out_router, out_idx, M);
}

// round 7
// speedup vs baseline: 4.5232x; 1.8212x over previous
#include <cuda_runtime.h>
#include <cuda_bf16.h>
#include <math.h>
#include <stdint.h>

#define MTOT 32768
#define CDIM 1024
#define HDIM 4096
#define EDIM 8

// ---- GEMM1 tiling: 128x128 CTA tile, BK=32, 8 warps of 64x32, 3 cp.async stages ----
#define ROWB   80
#define OFF_AH 0
#define OFF_AL 10240
#define OFF_BH 20480
#define OFF_BL 30720
#define STAGE  40960
#define SMEM_TOT (3 * STAGE)      // 122880 bytes

// ---- skinny scores GEMM: 128 rows/CTA, BK=64, 3 stages, 144B row stride ----
#define SK_ROWB  144
#define SK_OFFAL 18432
#define SK_STAGE 36864
#define SK_SMEM  (3 * SK_STAGE)   // 110592 bytes

// ---------------- device globals (no runtime allocation allowed) ----------------
__device__ __nv_bfloat16 g_xh[(size_t)MTOT*CDIM], g_xl[(size_t)MTOT*CDIM];   // x split
__device__ __nv_bfloat16 g_w1h[(size_t)HDIM*CDIM], g_w1l[(size_t)HDIM*CDIM]; // W1^T split [N][K]
__device__ __nv_bfloat16 g_hh[(size_t)MTOT*HDIM], g_hl[(size_t)MTOT*HDIM];   // h split
__device__ __nv_bfloat16 g_w2tqh[(size_t)EDIM*HDIM], g_w2tql[(size_t)EDIM*HDIM]; // (W2@tq^T)^T split [E][H]
__device__ float g_b2tq[EDIM];
__device__ float g_scores[(size_t)MTOT*EDIM];

// ---------------- PTX helpers (base sm_100-compatible PTX only) ----------------
__device__ __forceinline__ uint32_t smem_u32(const void* p) {
    uint32_t a;
    asm("{ .reg .u64 t; cvta.to.shared.u64 t, %1; cvt.u32.u64 %0, t; }" : "=r"(a) : "l"(p));
    return a;
}
__device__ __forceinline__ void cpa16(uint32_t d, const void* s) {
    asm volatile("cp.async.cg.shared.global [%0], [%1], 16;" :: "r"(d), "l"(s));
}
#define CP_COMMIT() asm volatile("cp.async.commit_group;" ::: "memory")
#define CP_WAIT1()  asm volatile("cp.async.wait_group 1;" ::: "memory")

__device__ __forceinline__ void ldsm4(uint32_t* r, uint32_t a) {
    asm volatile("ldmatrix.sync.aligned.m8n8.x4.shared.b16 {%0,%1,%2,%3}, [%4];"
        : "=r"(r[0]), "=r"(r[1]), "=r"(r[2]), "=r"(r[3]) : "r"(a));
}
__device__ __forceinline__ void mma16816(float* c, const uint32_t* a, const uint32_t* b) {
    asm volatile("mma.sync.aligned.m16n8k16.row.col.f32.bf16.bf16.f32 "
        "{%0,%1,%2,%3}, {%4,%5,%6,%7}, {%8,%9}, {%0,%1,%2,%3};"
        : "+f"(c[0]), "+f"(c[1]), "+f"(c[2]), "+f"(c[3])
        : "r"(a[0]), "r"(a[1]), "r"(a[2]), "r"(a[3]), "r"(b[0]), "r"(b[1]));
}

__device__ __forceinline__ float gelu_exact(float v) {
    return 0.5f * v * (1.0f + erff(v * 0.70710678118654752440f));
}

// ---------------- prep kernels ----------------
__global__ void __launch_bounds__(256)
split_x_kernel(const float* __restrict__ in, __nv_bfloat16* __restrict__ hi,
               __nv_bfloat16* __restrict__ lo, int n4)
{
    int i = blockIdx.x * blockDim.x + threadIdx.x;
    if (i >= n4) return;
    float4 v = ((const float4*)in)[i];
    __nv_bfloat16 h0 = __float2bfloat16(v.x), h1 = __float2bfloat16(v.y);
    __nv_bfloat16 h2 = __float2bfloat16(v.z), h3 = __float2bfloat16(v.w);
    __nv_bfloat16 l0 = __float2bfloat16(v.x - __bfloat162float(h0));
    __nv_bfloat16 l1 = __float2bfloat16(v.y - __bfloat162float(h1));
    __nv_bfloat16 l2 = __float2bfloat16(v.z - __bfloat162float(h2));
    __nv_bfloat16 l3 = __float2bfloat16(v.w - __bfloat162float(h3));
    uint2 hh, ll;
    hh.x = (uint32_t)__bfloat16_as_ushort(h0) | ((uint32_t)__bfloat16_as_ushort(h1) << 16);
    hh.y = (uint32_t)__bfloat16_as_ushort(h2) | ((uint32_t)__bfloat16_as_ushort(h3) << 16);
    ll.x = (uint32_t)__bfloat16_as_ushort(l0) | ((uint32_t)__bfloat16_as_ushort(l1) << 16);
    ll.y = (uint32_t)__bfloat16_as_ushort(l2) | ((uint32_t)__bfloat16_as_ushort(l3) << 16);
    ((uint2*)hi)[i] = hh;
    ((uint2*)lo)[i] = ll;
}

// W1 [K][N] row-major -> T [N][K] bf16 hi/lo
__global__ void __launch_bounds__(1024)
tsplit_kernel(const float* __restrict__ W, __nv_bfloat16* __restrict__ Th,
              __nv_bfloat16* __restrict__ Tl, int K, int N)
{
    __shared__ float t[32][33];
    int n0 = blockIdx.x * 32, k0 = blockIdx.y * 32;
    t[threadIdx.y][threadIdx.x] = W[(size_t)(k0 + threadIdx.y) * N + n0 + threadIdx.x];
    __syncthreads();
    float v = t[threadIdx.x][threadIdx.y];
    int n = n0 + threadIdx.y, k = k0 + threadIdx.x;
    __nv_bfloat16 h = __float2bfloat16(v);
    Th[(size_t)n * K + k] = h;
    Tl[(size_t)n * K + k] = __float2bfloat16(v - __bfloat162float(h));
}

// W2tq[e][k] = sum_c W2[k][c] * tq[e][c]  (fp32, then split hi/lo)
// grid: 513 blocks x 256 threads. Blocks 0..511: 8 warps each = one k per warp.
// Block 512: b2tq[e] = sum_c b2[c] * tq[e][c].
__global__ void __launch_bounds__(256)
w2tq_kernel(const float* __restrict__ W2, const float* __restrict__ tq,
            const float* __restrict__ b2,
            __nv_bfloat16* __restrict__ Bh, __nv_bfloat16* __restrict__ Bl,
            float* __restrict__ b2tq)
{
    __shared__ float tqs[EDIM][CDIM];   // 32 KB
    for (int i = threadIdx.x; i < EDIM * CDIM; i += blockDim.x)
        ((float*)tqs)[i] = tq[i];
    __syncthreads();

    const int lane = threadIdx.x & 31;
    const int warp = threadIdx.x >> 5;

    if (blockIdx.x < 512) {
        const int k = blockIdx.x * 8 + warp;   // 0..4095
        const float* wr = W2 + (size_t)k * CDIM;
        float acc[EDIM];
#pragma unroll
        for (int e = 0; e < EDIM; e++) acc[e] = 0.f;
        for (int c = lane; c < CDIM; c += 32) {
            float wv = wr[c];
#pragma unroll
            for (int e = 0; e < EDIM; e++) acc[e] += wv * tqs[e][c];
        }
#pragma unroll
        for (int off = 16; off >= 1; off >>= 1)
#pragma unroll
            for (int e = 0; e < EDIM; e++)
                acc[e] += __shfl_xor_sync(0xffffffffu, acc[e], off);
        if (lane < EDIM) {
            float v = 0.f;
#pragma unroll
            for (int e = 0; e < EDIM; e++) if (lane == e) v = acc[e];
            __nv_bfloat16 h = __float2bfloat16(v);
            Bh[(size_t)lane * HDIM + k] = h;
            Bl[(size_t)lane * HDIM + k] = __float2bfloat16(v - __bfloat162float(h));
        }
    } else {
        // b2tq: warp e handles expert e
        if (warp < EDIM) {
            float a = 0.f;
            for (int c = lane; c < CDIM; c += 32) a += b2[c] * tqs[warp][c];
#pragma unroll
            for (int off = 16; off >= 1; off >>= 1)
                a += __shfl_xor_sync(0xffffffffu, a, off);
            if (lane == 0) b2tq[warp] = a;
        }
    }
}

// ---------------- GEMM1 stage loader (unchanged from R6) ----------------
template<int KTOT>
__device__ __forceinline__ void issue_stage(
    const __nv_bfloat16* __restrict__ Ah, const __nv_bfloat16* __restrict__ Al,
    const __nv_bfloat16* __restrict__ Bh, const __nv_bfloat16* __restrict__ Bl,
    uint32_t stage_base, int kblk, int tid)
{
    const size_t kb = (size_t)kblk * 32;
#pragma unroll
    for (int j = 0; j < 2; j++) {
        int idx = tid + j * 256;
        int r = idx >> 2, ch = idx & 3;
        uint32_t so = stage_base + r * ROWB + ch * 16;
        size_t go = (size_t)r * KTOT + kb + ch * 8;
        cpa16(so + OFF_AH, Ah + go);
        cpa16(so + OFF_AL, Al + go);
        cpa16(so + OFF_BH, Bh + go);
        cpa16(so + OFF_BL, Bl + go);
    }
}

// ---------------- GEMM1: h = GELU(x@W1^T + b1), bf16-split output (unchanged from R6) ----------------
template<int KTOT, int NOUT, int GELU_EPI>
__global__ void __launch_bounds__(256, 1)
gemm_mma(const __nv_bfloat16* __restrict__ Ah, const __nv_bfloat16* __restrict__ Al,
         const __nv_bfloat16* __restrict__ Bh, const __nv_bfloat16* __restrict__ Bl,
         const float* __restrict__ bias,
         float* __restrict__ Cf, __nv_bfloat16* __restrict__ Ch, __nv_bfloat16* __restrict__ Cl)
{
    extern __shared__ __align__(128) char smem[];
    const uint32_t sb = smem_u32(smem);
    const int tid = threadIdx.x;
    const int wid = tid >> 5, lane = tid & 31;
    const int warp_m = wid >> 2, warp_n = wid & 3;
    const int bx = blockIdx.x, by = blockIdx.y;
    constexpr int NCH = KTOT / 32;

    const __nv_bfloat16* At_h = Ah + (size_t)(by * 128) * KTOT;
    const __nv_bfloat16* At_l = Al + (size_t)(by * 128) * KTOT;
    const __nv_bfloat16* Bt_h = Bh + (size_t)(bx * 128) * KTOT;
    const __nv_bfloat16* Bt_l = Bl + (size_t)(bx * 128) * KTOT;

    float acc[4][4][4];
#pragma unroll
    for (int i = 0; i < 4; i++)
#pragma unroll
        for (int j = 0; j < 4; j++)
#pragma unroll
            for (int k = 0; k < 4; k++) acc[i][j][k] = 0.f;

    issue_stage<KTOT>(At_h, At_l, Bt_h, Bt_l, sb + 0 * STAGE, 0, tid);
    CP_COMMIT();
    issue_stage<KTOT>(At_h, At_l, Bt_h, Bt_l, sb + 1 * STAGE, 1, tid);
    CP_COMMIT();
    CP_WAIT1();
    __syncthreads();

    const int aRow = warp_m * 64 + (lane & 15);
    const int aCol16 = (lane >> 4) * 16;
    const int bRow = warp_n * 32 + (lane & 7) + ((lane >> 4) << 3);
    const int bCol16 = ((lane >> 3) & 1) * 16;

#pragma unroll 1
    for (int c = 0; c < NCH; c++) {
        const uint32_t st = sb + (c % 3) * STAGE;
        if (c + 2 < NCH)
            issue_stage<KTOT>(At_h, At_l, Bt_h, Bt_l, sb + ((c + 2) % 3) * STAGE, c + 2, tid);
        CP_COMMIT();

#pragma unroll
        for (int ks = 0; ks < 2; ks++) {
            uint32_t ahf[4][4], alf[4][4], bhf[2][4], blf[2][4];
#pragma unroll
            for (int mt = 0; mt < 4; mt++) {
                uint32_t ad = st + OFF_AH + (uint32_t)(aRow + mt * 16) * ROWB + aCol16 + ks * 32;
                ldsm4(ahf[mt], ad);
                ldsm4(alf[mt], ad + (OFF_AL - OFF_AH));
            }
#pragma unroll
            for (int nh = 0; nh < 2; nh++) {
                uint32_t bd = st + OFF_BH + (uint32_t)(bRow + nh * 16) * ROWB + bCol16 + ks * 32;
                ldsm4(bhf[nh], bd);
                ldsm4(blf[nh], bd + (OFF_BL - OFF_BH));
            }
#pragma unroll
            for (int mt = 0; mt < 4; mt++)
#pragma unroll
                for (int nt = 0; nt < 4; nt++) {
                    const uint32_t* bh2 = &bhf[nt >> 1][(nt & 1) * 2];
                    const uint32_t* bl2 = &blf[nt >> 1][(nt & 1) * 2];
                    mma16816(acc[mt][nt], ahf[mt], bh2);
                    mma16816(acc[mt][nt], ahf[mt], bl2);
                    mma16816(acc[mt][nt], alf[mt], bh2);
                }
        }
        CP_WAIT1();
        __syncthreads();
    }

#pragma unroll
    for (int mt = 0; mt < 4; mt++) {
        const int row0 = by * 128 + warp_m * 64 + mt * 16 + (lane >> 2);
#pragma unroll
        for (int nt = 0; nt < 4; nt++) {
            const int col = bx * 128 + warp_n * 32 + nt * 8 + (lane & 3) * 2;
            const float bv0 = __ldg(bias + col), bv1 = __ldg(bias + col + 1);
#pragma unroll
            for (int half = 0; half < 2; half++) {
                const int row = row0 + half * 8;
                float v0 = acc[mt][nt][half * 2 + 0] + bv0;
                float v1 = acc[mt][nt][half * 2 + 1] + bv1;
                if (GELU_EPI) {
                    v0 = gelu_exact(v0); v1 = gelu_exact(v1);
                    __nv_bfloat16 h0 = __float2bfloat16(v0), h1 = __float2bfloat16(v1);
                    __nv_bfloat16 l0 = __float2bfloat16(v0 - __bfloat162float(h0));
                    __nv_bfloat16 l1 = __float2bfloat16(v1 - __bfloat162float(h1));
                    uint32_t ph = (uint32_t)__bfloat16_as_ushort(h0) | ((uint32_t)__bfloat16_as_ushort(h1) << 16);
                    uint32_t pl = (uint32_t)__bfloat16_as_ushort(l0) | ((uint32_t)__bfloat16_as_ushort(l1) << 16);
                    *(uint32_t*)(Ch + (size_t)row * NOUT + col) = ph;
                    *(uint32_t*)(Cl + (size_t)row * NOUT + col) = pl;
                } else {
                    *(float2*)(Cf + (size_t)row * NOUT + col) = make_float2(v0, v1);
                }
            }
        }
    }
}

// ---------------- skinny scores GEMM: S[M][8] = (hh+hl) @ (W2tq_h+W2tq_l)^T ----------------
// A [M][HDIM] bf16 hi/lo, B [8][HDIM] bf16 hi/lo. 3-term. 128 rows/CTA, 128 threads, BK=64.
__global__ void __launch_bounds__(128, 2)
skinny_scores(const __nv_bfloat16* __restrict__ Ah, const __nv_bfloat16* __restrict__ Al,
              const __nv_bfloat16* __restrict__ Bh, const __nv_bfloat16* __restrict__ Bl,
              float* __restrict__ S)
{
    extern __shared__ __align__(128) char smem[];
    const uint32_t sb = smem_u32(smem);
    const int tid = threadIdx.x;
    const int wid = tid >> 5, lane = tid & 31;
    const int row0 = blockIdx.x * 128;
    constexpr int NCH = HDIM / 64;   // 64 chunks

    const __nv_bfloat16* At_h = Ah + (size_t)row0 * HDIM;
    const __nv_bfloat16* At_l = Al + (size_t)row0 * HDIM;

    float acc[2][4];
#pragma unroll
    for (int i = 0; i < 2; i++)
#pragma unroll
        for (int j = 0; j < 4; j++) acc[i][j] = 0.f;

    // loader lambda-ish: 16 cp.async per thread per stage (8 per array)
    auto issue = [&](uint32_t base, int kblk) {
        const size_t kb = (size_t)kblk * 64;
#pragma unroll
        for (int j = 0; j < 8; j++) {
            int idx = tid + j * 128;
            int r = idx >> 3, ch = idx & 7;
            uint32_t so = base + r * SK_ROWB + ch * 16;
            size_t go = (size_t)r * HDIM + kb + ch * 8;
            cpa16(so, At_h + go);
            cpa16(so + SK_OFFAL, At_l + go);
        }
    };

    issue(sb + 0 * SK_STAGE, 0); CP_COMMIT();
    issue(sb + 1 * SK_STAGE, 1); CP_COMMIT();
    CP_WAIT1();
    __syncthreads();

    const int aRowOff = wid * 32 + (lane & 15);
    const int aCol16 = (lane >> 4) * 16;
    const int bn = lane >> 2;            // 0..7
    const int bk0 = (lane & 3) * 2;      // 0,2,4,6

#pragma unroll 1
    for (int c = 0; c < NCH; c++) {
        const uint32_t st = sb + (c % 3) * SK_STAGE;
        if (c + 2 < NCH) issue(sb + ((c + 2) % 3) * SK_STAGE, c + 2);
        CP_COMMIT();

#pragma unroll
        for (int ks = 0; ks < 4; ks++) {
            const int kbase = c * 64 + ks * 16;
            uint32_t bh[2], bl[2];
            bh[0] = __ldg((const uint32_t*)(Bh + (size_t)bn * HDIM + kbase + bk0));
            bh[1] = __ldg((const uint32_t*)(Bh + (size_t)bn * HDIM + kbase + bk0 + 8));
            bl[0] = __ldg((const uint32_t*)(Bl + (size_t)bn * HDIM + kbase + bk0));
            bl[1] = __ldg((const uint32_t*)(Bl + (size_t)bn * HDIM + kbase + bk0 + 8));
#pragma unroll
            for (int mt = 0; mt < 2; mt++) {
                uint32_t ahf[4], alf[4];
                uint32_t ad = st + (uint32_t)(aRowOff + mt * 16) * SK_ROWB + aCol16 + ks * 32;
                ldsm4(ahf, ad);
                ldsm4(alf, ad + SK_OFFAL);
                mma16816(acc[mt], ahf, bh);
                mma16816(acc[mt], ahf, bl);
                mma16816(acc[mt], alf, bh);
            }
        }
        CP_WAIT1();
        __syncthreads();
    }

#pragma unroll
    for (int mt = 0; mt < 2; mt++) {
        const int r0 = row0 + wid * 32 + mt * 16 + (lane >> 2);
        const int col = (lane & 3) * 2;
#pragma unroll
        for (int half = 0; half < 2; half++) {
            *(float2*)(S + (size_t)(r0 + half * 8) * EDIM + col) =
                make_float2(acc[mt][half * 2], acc[mt][half * 2 + 1]);
        }
    }
}

// ---------------- routing tail: scores precomputed; gate + top-2 + sparse softmax ----------------
__global__ void __launch_bounds__(256)
route_kernel(const float* __restrict__ S, const float* __restrict__ x,
             const float* __restrict__ noise,
             const float* __restrict__ nw, const float* __restrict__ nb,
             const float* __restrict__ temp_p, const float* __restrict__ b2tq,
             float* __restrict__ out_router, float* __restrict__ out_idx, int M)
{
    __shared__ float nws[CDIM];
    __shared__ float b2s[EDIM];
    for (int i = threadIdx.x; i < CDIM; i += blockDim.x) nws[i] = nw[i];
    if (threadIdx.x < EDIM) b2s[threadIdx.x] = b2tq[threadIdx.x];
    __syncthreads();

    const int lane = threadIdx.x & 31;
    const int warp = threadIdx.x >> 5;
    const float temp = *temp_p;
    const float nbv  = *nb;

    for (int t = blockIdx.x * 8 + warp; t < M; t += gridDim.x * 8) {
        const float* xr = x + (size_t)t * CDIM;
        float accg = 0.f;
        for (int j = lane; j < CDIM; j += 32) accg += xr[j] * nws[j];
#pragma unroll
        for (int off = 16; off >= 1; off >>= 1)
            accg += __shfl_xor_sync(0xffffffffu, accg, off);

        float gate = 1.f / (1.f + expf(-(accg + nbv)));

        // all lanes read the same 8 scores (warp-uniform address -> L1 broadcast)
        const float4* sp = (const float4*)(S + (size_t)t * EDIM);
        float4 s0 = sp[0], s1 = sp[1];
        float sc[EDIM] = { s0.x, s0.y, s0.z, s0.w, s1.x, s1.y, s1.z, s1.w };

        float noisy[EDIM];
#pragma unroll
        for (int e = 0; e < EDIM; e++)
            noisy[e] = sc[e] + b2s[e] + temp * noise[(size_t)t * EDIM + e] * gate;

        int i0 = 0; float v0 = noisy[0];
#pragma unroll
        for (int e = 1; e < EDIM; e++)
            if (noisy[e] > v0) { v0 = noisy[e]; i0 = e; }
        int i1 = -1; float v1 = -INFINITY;
#pragma unroll
        for (int e = 0; e < EDIM; e++)
            if (e != i0 && noisy[e] > v1) { v1 = noisy[e]; i1 = e; }

        float inv = 1.f / (temp + 1e-6f);
        float e1 = expf((v1 - v0) * inv);
        float denom = 1.f + e1;
        float p0 = 1.f / denom;
        float p1 = e1 / denom;

        if (lane < EDIM) {
            float pv = (lane == i0) ? p0 : ((lane == i1) ? p1 : 0.f);
            out_router[(size_t)t * EDIM + lane] = pv;
        }
        if (out_idx != nullptr && lane == 0) {
            out_idx[(size_t)t * 2 + 0] = (float)i0;
            out_idx[(size_t)t * 2 + 1] = (float)i1;
        }
    }
}

// ---------------- launch ----------------
extern "C" void kernel_launch(void* const* d_in, const int* in_sizes, int n_in,
                              void* d_out, int out_size)
{
    const float* x     = (const float*)d_in[0];
    const float* noise = (const float*)d_in[1];
    const float* W1    = (const float*)d_in[2];
    const float* b1    = (const float*)d_in[3];
    const float* W2    = (const float*)d_in[4];
    const float* b2    = (const float*)d_in[5];
    const float* tq    = (const float*)d_in[6];
    const float* nw    = (const float*)d_in[7];
    const float* nb    = (const float*)d_in[8];
    const float* temp  = (const float*)d_in[9];

    const int M = in_sizes[0] / CDIM;   // 32768

    __nv_bfloat16 *xh, *xl, *w1h, *w1l, *hh, *hl, *w2tqh, *w2tql;
    float *scores, *b2tqp;
    cudaGetSymbolAddress((void**)&xh,  g_xh);    cudaGetSymbolAddress((void**)&xl,  g_xl);
    cudaGetSymbolAddress((void**)&w1h, g_w1h);   cudaGetSymbolAddress((void**)&w1l, g_w1l);
    cudaGetSymbolAddress((void**)&hh,  g_hh);    cudaGetSymbolAddress((void**)&hl,  g_hl);
    cudaGetSymbolAddress((void**)&w2tqh, g_w2tqh); cudaGetSymbolAddress((void**)&w2tql, g_w2tql);
    cudaGetSymbolAddress((void**)&scores, g_scores); cudaGetSymbolAddress((void**)&b2tqp, g_b2tq);

    cudaFuncSetAttribute(gemm_mma<CDIM, HDIM, 1>, cudaFuncAttributeMaxDynamicSharedMemorySize, SMEM_TOT);
    cudaFuncSetAttribute(skinny_scores, cudaFuncAttributeMaxDynamicSharedMemorySize, SK_SMEM);

    // prep: split x, transpose+split W1, fold W2 into tq
    int n4 = (M * CDIM) / 4;
    split_x_kernel<<<(n4 + 255) / 256, 256>>>(x, xh, xl, n4);
    tsplit_kernel<<<dim3(HDIM / 32, CDIM / 32), dim3(32, 32)>>>(W1, w1h, w1l, CDIM, HDIM);
    w2tq_kernel<<<513, 256>>>(W2, tq, b2, w2tqh, w2tql, b2tqp);

    // GEMM1: h = GELU(x@W1+b1), stored as bf16 split
    gemm_mma<CDIM, HDIM, 1><<<dim3(HDIM / 128, M / 128), 256, SMEM_TOT>>>(
        xh, xl, w1h, w1l, b1, nullptr, hh, hl);

    // skinny GEMM: scores = h @ W2tq^T  (tall-skinny, memory-bound)
    skinny_scores<<<M / 128, 128, SK_SMEM>>>(hh, hl, w2tqh, w2tql, scores);

    float* out = (float*)d_out;
    float* out_router = out;
    float* out_idx = nullptr;
    if (out_size >= M * EDIM + M * 2)
        out_idx = out + (size_t)M * EDIM;

    route_kernel<<<M / 8, 256>>>(scores, x, noise, nw, nb, temp, b2tqp,
                                 out_router, out_idx, M);
}

// round 8
// speedup vs baseline: 4.7954x; 1.0602x over previous
#include <cuda_runtime.h>
#include <cuda_bf16.h>
#include <math.h>
#include <stdint.h>

#define MTOT 32768
#define CDIM 1024
#define HDIM 4096
#define EDIM 8

// ---- GEMM1 tiling: 128x128 CTA tile, BK=32, 16 warps of 32x32, 3 cp.async stages ----
#define ROWB   80
#define OFF_AH 0
#define OFF_AL 10240
#define OFF_BH 20480
#define OFF_BL 30720
#define STAGE  40960
#define SMEM_TOT (3 * STAGE)      // 122880 bytes

// ---- skinny scores GEMM: 128 rows/CTA, BK=64, 3 stages, 144B row stride ----
#define SK_ROWB  144
#define SK_OFFAL 18432
#define SK_STAGE 36864
#define SK_SMEM  (3 * SK_STAGE)   // 110592 bytes

// ---------------- device globals (no runtime allocation allowed) ----------------
__device__ __nv_bfloat16 g_xh[(size_t)MTOT*CDIM], g_xl[(size_t)MTOT*CDIM];   // x split
__device__ __nv_bfloat16 g_w1h[(size_t)HDIM*CDIM], g_w1l[(size_t)HDIM*CDIM]; // W1^T split [N][K]
__device__ __nv_bfloat16 g_hh[(size_t)MTOT*HDIM], g_hl[(size_t)MTOT*HDIM];   // h split
__device__ __nv_bfloat16 g_w2tqh[(size_t)EDIM*HDIM], g_w2tql[(size_t)EDIM*HDIM]; // (W2@tq^T)^T split [E][H]
__device__ float g_b2tq[EDIM];
__device__ float g_scores[(size_t)MTOT*EDIM];

// ---------------- PTX helpers (base sm_100-compatible PTX only) ----------------
__device__ __forceinline__ uint32_t smem_u32(const void* p) {
    uint32_t a;
    asm("{ .reg .u64 t; cvta.to.shared.u64 t, %1; cvt.u32.u64 %0, t; }" : "=r"(a) : "l"(p));
    return a;
}
__device__ __forceinline__ void cpa16(uint32_t d, const void* s) {
    asm volatile("cp.async.cg.shared.global [%0], [%1], 16;" :: "r"(d), "l"(s));
}
#define CP_COMMIT() asm volatile("cp.async.commit_group;" ::: "memory")
#define CP_WAIT1()  asm volatile("cp.async.wait_group 1;" ::: "memory")

__device__ __forceinline__ void ldsm4(uint32_t* r, uint32_t a) {
    asm volatile("ldmatrix.sync.aligned.m8n8.x4.shared.b16 {%0,%1,%2,%3}, [%4];"
        : "=r"(r[0]), "=r"(r[1]), "=r"(r[2]), "=r"(r[3]) : "r"(a));
}
__device__ __forceinline__ void mma16816(float* c, const uint32_t* a, const uint32_t* b) {
    asm volatile("mma.sync.aligned.m16n8k16.row.col.f32.bf16.bf16.f32 "
        "{%0,%1,%2,%3}, {%4,%5,%6,%7}, {%8,%9}, {%0,%1,%2,%3};"
        : "+f"(c[0]), "+f"(c[1]), "+f"(c[2]), "+f"(c[3])
        : "r"(a[0]), "r"(a[1]), "r"(a[2]), "r"(a[3]), "r"(b[0]), "r"(b[1]));
}

__device__ __forceinline__ float gelu_exact(float v) {
    return 0.5f * v * (1.0f + erff(v * 0.70710678118654752440f));
}

// ---------------- prep kernels ----------------
__global__ void __launch_bounds__(256)
split_x_kernel(const float* __restrict__ in, __nv_bfloat16* __restrict__ hi,
               __nv_bfloat16* __restrict__ lo, int n4)
{
    int i = blockIdx.x * blockDim.x + threadIdx.x;
    if (i >= n4) return;
    float4 v = ((const float4*)in)[i];
    __nv_bfloat16 h0 = __float2bfloat16(v.x), h1 = __float2bfloat16(v.y);
    __nv_bfloat16 h2 = __float2bfloat16(v.z), h3 = __float2bfloat16(v.w);
    __nv_bfloat16 l0 = __float2bfloat16(v.x - __bfloat162float(h0));
    __nv_bfloat16 l1 = __float2bfloat16(v.y - __bfloat162float(h1));
    __nv_bfloat16 l2 = __float2bfloat16(v.z - __bfloat162float(h2));
    __nv_bfloat16 l3 = __float2bfloat16(v.w - __bfloat162float(h3));
    uint2 hh, ll;
    hh.x = (uint32_t)__bfloat16_as_ushort(h0) | ((uint32_t)__bfloat16_as_ushort(h1) << 16);
    hh.y = (uint32_t)__bfloat16_as_ushort(h2) | ((uint32_t)__bfloat16_as_ushort(h3) << 16);
    ll.x = (uint32_t)__bfloat16_as_ushort(l0) | ((uint32_t)__bfloat16_as_ushort(l1) << 16);
    ll.y = (uint32_t)__bfloat16_as_ushort(l2) | ((uint32_t)__bfloat16_as_ushort(l3) << 16);
    ((uint2*)hi)[i] = hh;
    ((uint2*)lo)[i] = ll;
}

// W1 [K][N] row-major -> T [N][K] bf16 hi/lo
__global__ void __launch_bounds__(1024)
tsplit_kernel(const float* __restrict__ W, __nv_bfloat16* __restrict__ Th,
              __nv_bfloat16* __restrict__ Tl, int K, int N)
{
    __shared__ float t[32][33];
    int n0 = blockIdx.x * 32, k0 = blockIdx.y * 32;
    t[threadIdx.y][threadIdx.x] = W[(size_t)(k0 + threadIdx.y) * N + n0 + threadIdx.x];
    __syncthreads();
    float v = t[threadIdx.x][threadIdx.y];
    int n = n0 + threadIdx.y, k = k0 + threadIdx.x;
    __nv_bfloat16 h = __float2bfloat16(v);
    Th[(size_t)n * K + k] = h;
    Tl[(size_t)n * K + k] = __float2bfloat16(v - __bfloat162float(h));
}

// W2tq[e][k] = sum_c W2[k][c] * tq[e][c]  (fp32, then split hi/lo)
__global__ void __launch_bounds__(256)
w2tq_kernel(const float* __restrict__ W2, const float* __restrict__ tq,
            const float* __restrict__ b2,
            __nv_bfloat16* __restrict__ Bh, __nv_bfloat16* __restrict__ Bl,
            float* __restrict__ b2tq)
{
    __shared__ float tqs[EDIM][CDIM];   // 32 KB
    for (int i = threadIdx.x; i < EDIM * CDIM; i += blockDim.x)
        ((float*)tqs)[i] = tq[i];
    __syncthreads();

    const int lane = threadIdx.x & 31;
    const int warp = threadIdx.x >> 5;

    if (blockIdx.x < 512) {
        const int k = blockIdx.x * 8 + warp;
        const float* wr = W2 + (size_t)k * CDIM;
        float acc[EDIM];
#pragma unroll
        for (int e = 0; e < EDIM; e++) acc[e] = 0.f;
        for (int c = lane; c < CDIM; c += 32) {
            float wv = wr[c];
#pragma unroll
            for (int e = 0; e < EDIM; e++) acc[e] += wv * tqs[e][c];
        }
#pragma unroll
        for (int off = 16; off >= 1; off >>= 1)
#pragma unroll
            for (int e = 0; e < EDIM; e++)
                acc[e] += __shfl_xor_sync(0xffffffffu, acc[e], off);
        if (lane < EDIM) {
            float v = 0.f;
#pragma unroll
            for (int e = 0; e < EDIM; e++) if (lane == e) v = acc[e];
            __nv_bfloat16 h = __float2bfloat16(v);
            Bh[(size_t)lane * HDIM + k] = h;
            Bl[(size_t)lane * HDIM + k] = __float2bfloat16(v - __bfloat162float(h));
        }
    } else {
        if (warp < EDIM) {
            float a = 0.f;
            for (int c = lane; c < CDIM; c += 32) a += b2[c] * tqs[warp][c];
#pragma unroll
            for (int off = 16; off >= 1; off >>= 1)
                a += __shfl_xor_sync(0xffffffffu, a, off);
            if (lane == 0) b2tq[warp] = a;
        }
    }
}

// ---------------- GEMM1 stage loader (512 threads: 1 chunk per thread per array) ----------------
template<int KTOT>
__device__ __forceinline__ void issue_stage512(
    const __nv_bfloat16* __restrict__ Ah, const __nv_bfloat16* __restrict__ Al,
    const __nv_bfloat16* __restrict__ Bh, const __nv_bfloat16* __restrict__ Bl,
    uint32_t stage_base, int kblk, int tid)
{
    const size_t kb = (size_t)kblk * 32;
    int r = tid >> 2, ch = tid & 3;
    uint32_t so = stage_base + r * ROWB + ch * 16;
    size_t go = (size_t)r * KTOT + kb + ch * 8;
    cpa16(so + OFF_AH, Ah + go);
    cpa16(so + OFF_AL, Al + go);
    cpa16(so + OFF_BH, Bh + go);
    cpa16(so + OFF_BL, Bl + go);
}

// ---------------- GEMM1: h = GELU(x@W1^T + b1), bf16-split output ----------------
// 512 threads, 16 warps (4x4), warp tile 32x32. 3-term bf16 split, fp32 acc.
template<int KTOT, int NOUT, int GELU_EPI>
__global__ void __launch_bounds__(512, 1)
gemm_mma(const __nv_bfloat16* __restrict__ Ah, const __nv_bfloat16* __restrict__ Al,
         const __nv_bfloat16* __restrict__ Bh, const __nv_bfloat16* __restrict__ Bl,
         const float* __restrict__ bias,
         float* __restrict__ Cf, __nv_bfloat16* __restrict__ Ch, __nv_bfloat16* __restrict__ Cl)
{
    extern __shared__ __align__(128) char smem[];
    const uint32_t sb = smem_u32(smem);
    const int tid = threadIdx.x;
    const int wid = tid >> 5, lane = tid & 31;
    const int warp_m = wid >> 2, warp_n = wid & 3;   // 4 x 4 warp grid, 32x32 per warp
    const int bx = blockIdx.x, by = blockIdx.y;
    constexpr int NCH = KTOT / 32;

    const __nv_bfloat16* At_h = Ah + (size_t)(by * 128) * KTOT;
    const __nv_bfloat16* At_l = Al + (size_t)(by * 128) * KTOT;
    const __nv_bfloat16* Bt_h = Bh + (size_t)(bx * 128) * KTOT;
    const __nv_bfloat16* Bt_l = Bl + (size_t)(bx * 128) * KTOT;

    float acc[2][4][4];
#pragma unroll
    for (int i = 0; i < 2; i++)
#pragma unroll
        for (int j = 0; j < 4; j++)
#pragma unroll
            for (int k = 0; k < 4; k++) acc[i][j][k] = 0.f;

    issue_stage512<KTOT>(At_h, At_l, Bt_h, Bt_l, sb + 0 * STAGE, 0, tid);
    CP_COMMIT();
    issue_stage512<KTOT>(At_h, At_l, Bt_h, Bt_l, sb + 1 * STAGE, 1, tid);
    CP_COMMIT();
    CP_WAIT1();
    __syncthreads();

    const int aRow = warp_m * 32 + (lane & 15);
    const int aCol16 = (lane >> 4) * 16;
    const int bRow = warp_n * 32 + (lane & 7) + ((lane >> 4) << 3);
    const int bCol16 = ((lane >> 3) & 1) * 16;

#pragma unroll 1
    for (int c = 0; c < NCH; c++) {
        const uint32_t st = sb + (c % 3) * STAGE;
        if (c + 2 < NCH)
            issue_stage512<KTOT>(At_h, At_l, Bt_h, Bt_l, sb + ((c + 2) % 3) * STAGE, c + 2, tid);
        CP_COMMIT();

#pragma unroll
        for (int ks = 0; ks < 2; ks++) {
            uint32_t ahf[2][4], alf[2][4], bhf[2][4], blf[2][4];
#pragma unroll
            for (int mt = 0; mt < 2; mt++) {
                uint32_t ad = st + OFF_AH + (uint32_t)(aRow + mt * 16) * ROWB + aCol16 + ks * 32;
                ldsm4(ahf[mt], ad);
                ldsm4(alf[mt], ad + (OFF_AL - OFF_AH));
            }
#pragma unroll
            for (int nh = 0; nh < 2; nh++) {
                uint32_t bd = st + OFF_BH + (uint32_t)(bRow + nh * 16) * ROWB + bCol16 + ks * 32;
                ldsm4(bhf[nh], bd);
                ldsm4(blf[nh], bd + (OFF_BL - OFF_BH));
            }
#pragma unroll
            for (int mt = 0; mt < 2; mt++)
#pragma unroll
                for (int nt = 0; nt < 4; nt++) {
                    const uint32_t* bh2 = &bhf[nt >> 1][(nt & 1) * 2];
                    const uint32_t* bl2 = &blf[nt >> 1][(nt & 1) * 2];
                    mma16816(acc[mt][nt], ahf[mt], bh2);
                    mma16816(acc[mt][nt], ahf[mt], bl2);
                    mma16816(acc[mt][nt], alf[mt], bh2);
                }
        }
        CP_WAIT1();
        __syncthreads();
    }

#pragma unroll
    for (int mt = 0; mt < 2; mt++) {
        const int row0 = by * 128 + warp_m * 32 + mt * 16 + (lane >> 2);
#pragma unroll
        for (int nt = 0; nt < 4; nt++) {
            const int col = bx * 128 + warp_n * 32 + nt * 8 + (lane & 3) * 2;
            const float bv0 = __ldg(bias + col), bv1 = __ldg(bias + col + 1);
#pragma unroll
            for (int half = 0; half < 2; half++) {
                const int row = row0 + half * 8;
                float v0 = acc[mt][nt][half * 2 + 0] + bv0;
                float v1 = acc[mt][nt][half * 2 + 1] + bv1;
                if (GELU_EPI) {
                    v0 = gelu_exact(v0); v1 = gelu_exact(v1);
                    __nv_bfloat16 h0 = __float2bfloat16(v0), h1 = __float2bfloat16(v1);
                    __nv_bfloat16 l0 = __float2bfloat16(v0 - __bfloat162float(h0));
                    __nv_bfloat16 l1 = __float2bfloat16(v1 - __bfloat162float(h1));
                    uint32_t ph = (uint32_t)__bfloat16_as_ushort(h0) | ((uint32_t)__bfloat16_as_ushort(h1) << 16);
                    uint32_t pl = (uint32_t)__bfloat16_as_ushort(l0) | ((uint32_t)__bfloat16_as_ushort(l1) << 16);
                    *(uint32_t*)(Ch + (size_t)row * NOUT + col) = ph;
                    *(uint32_t*)(Cl + (size_t)row * NOUT + col) = pl;
                } else {
                    *(float2*)(Cf + (size_t)row * NOUT + col) = make_float2(v0, v1);
                }
            }
        }
    }
}

// ---------------- skinny scores GEMM (unchanged from R7 pass) ----------------
__global__ void __launch_bounds__(128, 2)
skinny_scores(const __nv_bfloat16* __restrict__ Ah, const __nv_bfloat16* __restrict__ Al,
              const __nv_bfloat16* __restrict__ Bh, const __nv_bfloat16* __restrict__ Bl,
              float* __restrict__ S)
{
    extern __shared__ __align__(128) char smem[];
    const uint32_t sb = smem_u32(smem);
    const int tid = threadIdx.x;
    const int wid = tid >> 5, lane = tid & 31;
    const int row0 = blockIdx.x * 128;
    constexpr int NCH = HDIM / 64;

    const __nv_bfloat16* At_h = Ah + (size_t)row0 * HDIM;
    const __nv_bfloat16* At_l = Al + (size_t)row0 * HDIM;

    float acc[2][4];
#pragma unroll
    for (int i = 0; i < 2; i++)
#pragma unroll
        for (int j = 0; j < 4; j++) acc[i][j] = 0.f;

    auto issue = [&](uint32_t base, int kblk) {
        const size_t kb = (size_t)kblk * 64;
#pragma unroll
        for (int j = 0; j < 8; j++) {
            int idx = tid + j * 128;
            int r = idx >> 3, ch = idx & 7;
            uint32_t so = base + r * SK_ROWB + ch * 16;
            size_t go = (size_t)r * HDIM + kb + ch * 8;
            cpa16(so, At_h + go);
            cpa16(so + SK_OFFAL, At_l + go);
        }
    };

    issue(sb + 0 * SK_STAGE, 0); CP_COMMIT();
    issue(sb + 1 * SK_STAGE, 1); CP_COMMIT();
    CP_WAIT1();
    __syncthreads();

    const int aRowOff = wid * 32 + (lane & 15);
    const int aCol16 = (lane >> 4) * 16;
    const int bn = lane >> 2;
    const int bk0 = (lane & 3) * 2;

#pragma unroll 1
    for (int c = 0; c < NCH; c++) {
        const uint32_t st = sb + (c % 3) * SK_STAGE;
        if (c + 2 < NCH) issue(sb + ((c + 2) % 3) * SK_STAGE, c + 2);
        CP_COMMIT();

#pragma unroll
        for (int ks = 0; ks < 4; ks++) {
            const int kbase = c * 64 + ks * 16;
            uint32_t bh[2], bl[2];
            bh[0] = __ldg((const uint32_t*)(Bh + (size_t)bn * HDIM + kbase + bk0));
            bh[1] = __ldg((const uint32_t*)(Bh + (size_t)bn * HDIM + kbase + bk0 + 8));
            bl[0] = __ldg((const uint32_t*)(Bl + (size_t)bn * HDIM + kbase + bk0));
            bl[1] = __ldg((const uint32_t*)(Bl + (size_t)bn * HDIM + kbase + bk0 + 8));
#pragma unroll
            for (int mt = 0; mt < 2; mt++) {
                uint32_t ahf[4], alf[4];
                uint32_t ad = st + (uint32_t)(aRowOff + mt * 16) * SK_ROWB + aCol16 + ks * 32;
                ldsm4(ahf, ad);
                ldsm4(alf, ad + SK_OFFAL);
                mma16816(acc[mt], ahf, bh);
                mma16816(acc[mt], ahf, bl);
                mma16816(acc[mt], alf, bh);
            }
        }
        CP_WAIT1();
        __syncthreads();
    }

#pragma unroll
    for (int mt = 0; mt < 2; mt++) {
        const int r0 = row0 + wid * 32 + mt * 16 + (lane >> 2);
        const int col = (lane & 3) * 2;
#pragma unroll
        for (int half = 0; half < 2; half++) {
            *(float2*)(S + (size_t)(r0 + half * 8) * EDIM + col) =
                make_float2(acc[mt][half * 2], acc[mt][half * 2 + 1]);
        }
    }
}

// ---------------- routing tail (unchanged from R7 pass) ----------------
__global__ void __launch_bounds__(256)
route_kernel(const float* __restrict__ S, const float* __restrict__ x,
             const float* __restrict__ noise,
             const float* __restrict__ nw, const float* __restrict__ nb,
             const float* __restrict__ temp_p, const float* __restrict__ b2tq,
             float* __restrict__ out_router, float* __restrict__ out_idx, int M)
{
    __shared__ float nws[CDIM];
    __shared__ float b2s[EDIM];
    for (int i = threadIdx.x; i < CDIM; i += blockDim.x) nws[i] = nw[i];
    if (threadIdx.x < EDIM) b2s[threadIdx.x] = b2tq[threadIdx.x];
    __syncthreads();

    const int lane = threadIdx.x & 31;
    const int warp = threadIdx.x >> 5;
    const float temp = *temp_p;
    const float nbv  = *nb;

    for (int t = blockIdx.x * 8 + warp; t < M; t += gridDim.x * 8) {
        const float* xr = x + (size_t)t * CDIM;
        float accg = 0.f;
        for (int j = lane; j < CDIM; j += 32) accg += xr[j] * nws[j];
#pragma unroll
        for (int off = 16; off >= 1; off >>= 1)
            accg += __shfl_xor_sync(0xffffffffu, accg, off);

        float gate = 1.f / (1.f + expf(-(accg + nbv)));

        const float4* sp = (const float4*)(S + (size_t)t * EDIM);
        float4 s0 = sp[0], s1 = sp[1];
        float sc[EDIM] = { s0.x, s0.y, s0.z, s0.w, s1.x, s1.y, s1.z, s1.w };

        float noisy[EDIM];
#pragma unroll
        for (int e = 0; e < EDIM; e++)
            noisy[e] = sc[e] + b2s[e] + temp * noise[(size_t)t * EDIM + e] * gate;

        int i0 = 0; float v0 = noisy[0];
#pragma unroll
        for (int e = 1; e < EDIM; e++)
            if (noisy[e] > v0) { v0 = noisy[e]; i0 = e; }
        int i1 = -1; float v1 = -INFINITY;
#pragma unroll
        for (int e = 0; e < EDIM; e++)
            if (e != i0 && noisy[e] > v1) { v1 = noisy[e]; i1 = e; }

        float inv = 1.f / (temp + 1e-6f);
        float e1 = expf((v1 - v0) * inv);
        float denom = 1.f + e1;
        float p0 = 1.f / denom;
        float p1 = e1 / denom;

        if (lane < EDIM) {
            float pv = (lane == i0) ? p0 : ((lane == i1) ? p1 : 0.f);
            out_router[(size_t)t * EDIM + lane] = pv;
        }
        if (out_idx != nullptr && lane == 0) {
            out_idx[(size_t)t * 2 + 0] = (float)i0;
            out_idx[(size_t)t * 2 + 1] = (float)i1;
        }
    }
}

// ---------------- launch ----------------
extern "C" void kernel_launch(void* const* d_in, const int* in_sizes, int n_in,
                              void* d_out, int out_size)
{
    const float* x     = (const float*)d_in[0];
    const float* noise = (const float*)d_in[1];
    const float* W1    = (const float*)d_in[2];
    const float* b1    = (const float*)d_in[3];
    const float* W2    = (const float*)d_in[4];
    const float* b2    = (const float*)d_in[5];
    const float* tq    = (const float*)d_in[6];
    const float* nw    = (const float*)d_in[7];
    const float* nb    = (const float*)d_in[8];
    const float* temp  = (const float*)d_in[9];

    const int M = in_sizes[0] / CDIM;   // 32768

    __nv_bfloat16 *xh, *xl, *w1h, *w1l, *hh, *hl, *w2tqh, *w2tql;
    float *scores, *b2tqp;
    cudaGetSymbolAddress((void**)&xh,  g_xh);    cudaGetSymbolAddress((void**)&xl,  g_xl);
    cudaGetSymbolAddress((void**)&w1h, g_w1h);   cudaGetSymbolAddress((void**)&w1l, g_w1l);
    cudaGetSymbolAddress((void**)&hh,  g_hh);    cudaGetSymbolAddress((void**)&hl,  g_hl);
    cudaGetSymbolAddress((void**)&w2tqh, g_w2tqh); cudaGetSymbolAddress((void**)&w2tql, g_w2tql);
    cudaGetSymbolAddress((void**)&scores, g_scores); cudaGetSymbolAddress((void**)&b2tqp, g_b2tq);

    cudaFuncSetAttribute(gemm_mma<CDIM, HDIM, 1>, cudaFuncAttributeMaxDynamicSharedMemorySize, SMEM_TOT);
    cudaFuncSetAttribute(skinny_scores, cudaFuncAttributeMaxDynamicSharedMemorySize, SK_SMEM);

    // prep: split x, transpose+split W1, fold W2 into tq
    int n4 = (M * CDIM) / 4;
    split_x_kernel<<<(n4 + 255) / 256, 256>>>(x, xh, xl, n4);
    tsplit_kernel<<<dim3(HDIM / 32, CDIM / 32), dim3(32, 32)>>>(W1, w1h, w1l, CDIM, HDIM);
    w2tq_kernel<<<513, 256>>>(W2, tq, b2, w2tqh, w2tql, b2tqp);

    // GEMM1: h = GELU(x@W1+b1), stored as bf16 split (512 threads, 16 warps)
    gemm_mma<CDIM, HDIM, 1><<<dim3(HDIM / 128, M / 128), 512, SMEM_TOT>>>(
        xh, xl, w1h, w1l, b1, nullptr, hh, hl);

    // skinny GEMM: scores = h @ W2tq^T
    skinny_scores<<<M / 128, 128, SK_SMEM>>>(hh, hl, w2tqh, w2tql, scores);

    float* out = (float*)d_out;
    float* out_router = out;
    float* out_idx = nullptr;
    if (out_size >= M * EDIM + M * 2)
        out_idx = out + (size_t)M * EDIM;

    route_kernel<<<M / 8, 256>>>(scores, x, noise, nw, nb, temp, b2tqp,
                                 out_router, out_idx, M);
}

// round 10
// speedup vs baseline: 5.1979x; 1.0839x over previous
#include <cuda_runtime.h>
#include <cuda_bf16.h>
#include <math.h>
#include <stdint.h>

#define MTOT 32768
#define CDIM 1024
#define HDIM 4096
#define EDIM 8

// ---- GEMM1 tiling: 128x128 CTA tile, BK=64, 16 warps of 32x32, 3 cp.async stages ----
#define ROWB   144                 // 64 bf16 = 128B + 16B pad (ldsm conflict-free)
#define OFF_AH 0
#define OFF_AL 18432
#define OFF_BH 36864
#define OFF_BL 55296
#define STAGE  73728
#define SMEM_TOT (3 * STAGE)       // 221184 bytes (<= 227KB cap)

// ---- skinny scores GEMM: 128 rows/CTA, BK=64, 3 stages, 144B row stride ----
#define SK_ROWB  144
#define SK_OFFAL 18432
#define SK_STAGE 36864
#define SK_SMEM  (3 * SK_STAGE)    // 110592 bytes

// ---------------- device globals (no runtime allocation allowed) ----------------
__device__ __nv_bfloat16 g_xh[(size_t)MTOT*CDIM], g_xl[(size_t)MTOT*CDIM];   // x split
__device__ __nv_bfloat16 g_w1h[(size_t)HDIM*CDIM], g_w1l[(size_t)HDIM*CDIM]; // W1^T split [N][K]
__device__ __nv_bfloat16 g_hh[(size_t)MTOT*HDIM], g_hl[(size_t)MTOT*HDIM];   // h split
__device__ __nv_bfloat16 g_w2tqh[(size_t)EDIM*HDIM], g_w2tql[(size_t)EDIM*HDIM]; // (W2@tq^T)^T split [E][H]
__device__ float g_b2tq[EDIM];
__device__ float g_scores[(size_t)MTOT*EDIM];

// ---------------- PTX helpers (base sm_100-compatible PTX only) ----------------
__device__ __forceinline__ uint32_t smem_u32(const void* p) {
    uint32_t a;
    asm("{ .reg .u64 t; cvta.to.shared.u64 t, %1; cvt.u32.u64 %0, t; }" : "=r"(a) : "l"(p));
    return a;
}
__device__ __forceinline__ void cpa16(uint32_t d, const void* s) {
    asm volatile("cp.async.cg.shared.global [%0], [%1], 16;" :: "r"(d), "l"(s));
}
#define CP_COMMIT() asm volatile("cp.async.commit_group;" ::: "memory")
#define CP_WAIT1()  asm volatile("cp.async.wait_group 1;" ::: "memory")

__device__ __forceinline__ void ldsm4(uint32_t* r, uint32_t a) {
    asm volatile("ldmatrix.sync.aligned.m8n8.x4.shared.b16 {%0,%1,%2,%3}, [%4];"
        : "=r"(r[0]), "=r"(r[1]), "=r"(r[2]), "=r"(r[3]) : "r"(a));
}
__device__ __forceinline__ void mma16816(float* c, const uint32_t* a, const uint32_t* b) {
    asm volatile("mma.sync.aligned.m16n8k16.row.col.f32.bf16.bf16.f32 "
        "{%0,%1,%2,%3}, {%4,%5,%6,%7}, {%8,%9}, {%0,%1,%2,%3};"
        : "+f"(c[0]), "+f"(c[1]), "+f"(c[2]), "+f"(c[3])
        : "r"(a[0]), "r"(a[1]), "r"(a[2]), "r"(a[3]), "r"(b[0]), "r"(b[1]));
}

__device__ __forceinline__ float gelu_exact(float v) {
    return 0.5f * v * (1.0f + erff(v * 0.70710678118654752440f));
}

// ---------------- prep kernels ----------------
__global__ void __launch_bounds__(256)
split_x_kernel(const float* __restrict__ in, __nv_bfloat16* __restrict__ hi,
               __nv_bfloat16* __restrict__ lo, int n4)
{
    int i = blockIdx.x * blockDim.x + threadIdx.x;
    if (i >= n4) return;
    float4 v = ((const float4*)in)[i];
    __nv_bfloat16 h0 = __float2bfloat16(v.x), h1 = __float2bfloat16(v.y);
    __nv_bfloat16 h2 = __float2bfloat16(v.z), h3 = __float2bfloat16(v.w);
    __nv_bfloat16 l0 = __float2bfloat16(v.x - __bfloat162float(h0));
    __nv_bfloat16 l1 = __float2bfloat16(v.y - __bfloat162float(h1));
    __nv_bfloat16 l2 = __float2bfloat16(v.z - __bfloat162float(h2));
    __nv_bfloat16 l3 = __float2bfloat16(v.w - __bfloat162float(h3));
    uint2 hh, ll;
    hh.x = (uint32_t)__bfloat16_as_ushort(h0) | ((uint32_t)__bfloat16_as_ushort(h1) << 16);
    hh.y = (uint32_t)__bfloat16_as_ushort(h2) | ((uint32_t)__bfloat16_as_ushort(h3) << 16);
    ll.x = (uint32_t)__bfloat16_as_ushort(l0) | ((uint32_t)__bfloat16_as_ushort(l1) << 16);
    ll.y = (uint32_t)__bfloat16_as_ushort(l2) | ((uint32_t)__bfloat16_as_ushort(l3) << 16);
    ((uint2*)hi)[i] = hh;
    ((uint2*)lo)[i] = ll;
}

// W1 [K][N] row-major -> T [N][K] bf16 hi/lo
__global__ void __launch_bounds__(1024)
tsplit_kernel(const float* __restrict__ W, __nv_bfloat16* __restrict__ Th,
              __nv_bfloat16* __restrict__ Tl, int K, int N)
{
    __shared__ float t[32][33];
    int n0 = blockIdx.x * 32, k0 = blockIdx.y * 32;
    t[threadIdx.y][threadIdx.x] = W[(size_t)(k0 + threadIdx.y) * N + n0 + threadIdx.x];
    __syncthreads();
    float v = t[threadIdx.x][threadIdx.y];
    int n = n0 + threadIdx.y, k = k0 + threadIdx.x;
    __nv_bfloat16 h = __float2bfloat16(v);
    Th[(size_t)n * K + k] = h;
    Tl[(size_t)n * K + k] = __float2bfloat16(v - __bfloat162float(h));
}

// W2tq[e][k] = sum_c W2[k][c] * tq[e][c]  (fp32, then split hi/lo)
__global__ void __launch_bounds__(256)
w2tq_kernel(const float* __restrict__ W2, const float* __restrict__ tq,
            const float* __restrict__ b2,
            __nv_bfloat16* __restrict__ Bh, __nv_bfloat16* __restrict__ Bl,
            float* __restrict__ b2tq)
{
    __shared__ float tqs[EDIM][CDIM];   // 32 KB
    for (int i = threadIdx.x; i < EDIM * CDIM; i += blockDim.x)
        ((float*)tqs)[i] = tq[i];
    __syncthreads();

    const int lane = threadIdx.x & 31;
    const int warp = threadIdx.x >> 5;

    if (blockIdx.x < 512) {
        const int k = blockIdx.x * 8 + warp;
        const float* wr = W2 + (size_t)k * CDIM;
        float acc[EDIM];
#pragma unroll
        for (int e = 0; e < EDIM; e++) acc[e] = 0.f;
        for (int c = lane; c < CDIM; c += 32) {
            float wv = wr[c];
#pragma unroll
            for (int e = 0; e < EDIM; e++) acc[e] += wv * tqs[e][c];
        }
#pragma unroll
        for (int off = 16; off >= 1; off >>= 1)
#pragma unroll
            for (int e = 0; e < EDIM; e++)
                acc[e] += __shfl_xor_sync(0xffffffffu, acc[e], off);
        if (lane < EDIM) {
            float v = 0.f;
#pragma unroll
            for (int e = 0; e < EDIM; e++) if (lane == e) v = acc[e];
            __nv_bfloat16 h = __float2bfloat16(v);
            Bh[(size_t)lane * HDIM + k] = h;
            Bl[(size_t)lane * HDIM + k] = __float2bfloat16(v - __bfloat162float(h));
        }
    } else {
        if (warp < EDIM) {
            float a = 0.f;
            for (int c = lane; c < CDIM; c += 32) a += b2[c] * tqs[warp][c];
#pragma unroll
            for (int off = 16; off >= 1; off >>= 1)
                a += __shfl_xor_sync(0xffffffffu, a, off);
            if (lane == 0) b2tq[warp] = a;
        }
    }
}

// ---------------- GEMM1 stage loader (512 threads, BK=64: 2 chunks per thread per array) ----------------
template<int KTOT>
__device__ __forceinline__ void issue_stage512(
    const __nv_bfloat16* __restrict__ Ah, const __nv_bfloat16* __restrict__ Al,
    const __nv_bfloat16* __restrict__ Bh, const __nv_bfloat16* __restrict__ Bl,
    uint32_t stage_base, int kblk, int tid)
{
    const size_t kb = (size_t)kblk * 64;
#pragma unroll
    for (int j = 0; j < 2; j++) {
        int idx = tid + j * 512;
        int r = idx >> 3, ch = idx & 7;
        uint32_t so = stage_base + r * ROWB + ch * 16;
        size_t go = (size_t)r * KTOT + kb + ch * 8;
        cpa16(so + OFF_AH, Ah + go);
        cpa16(so + OFF_AL, Al + go);
        cpa16(so + OFF_BH, Bh + go);
        cpa16(so + OFF_BL, Bl + go);
    }
}

// ---------------- GEMM1: h = GELU(x@W1^T + b1), bf16-split output ----------------
// 512 threads, 16 warps (4x4), warp tile 32x32, BK=64 (4 ks-steps per barrier).
template<int KTOT, int NOUT, int GELU_EPI>
__global__ void __launch_bounds__(512, 1)
gemm_mma(const __nv_bfloat16* __restrict__ Ah, const __nv_bfloat16* __restrict__ Al,
         const __nv_bfloat16* __restrict__ Bh, const __nv_bfloat16* __restrict__ Bl,
         const float* __restrict__ bias,
         float* __restrict__ Cf, __nv_bfloat16* __restrict__ Ch, __nv_bfloat16* __restrict__ Cl)
{
    extern __shared__ __align__(128) char smem[];
    const uint32_t sb = smem_u32(smem);
    const int tid = threadIdx.x;
    const int wid = tid >> 5, lane = tid & 31;
    const int warp_m = wid >> 2, warp_n = wid & 3;   // 4 x 4 warp grid, 32x32 per warp
    const int bx = blockIdx.x, by = blockIdx.y;
    constexpr int NCH = KTOT / 64;

    const __nv_bfloat16* At_h = Ah + (size_t)(by * 128) * KTOT;
    const __nv_bfloat16* At_l = Al + (size_t)(by * 128) * KTOT;
    const __nv_bfloat16* Bt_h = Bh + (size_t)(bx * 128) * KTOT;
    const __nv_bfloat16* Bt_l = Bl + (size_t)(bx * 128) * KTOT;

    float acc[2][4][4];
#pragma unroll
    for (int i = 0; i < 2; i++)
#pragma unroll
        for (int j = 0; j < 4; j++)
#pragma unroll
            for (int k = 0; k < 4; k++) acc[i][j][k] = 0.f;

    issue_stage512<KTOT>(At_h, At_l, Bt_h, Bt_l, sb + 0 * STAGE, 0, tid);
    CP_COMMIT();
    issue_stage512<KTOT>(At_h, At_l, Bt_h, Bt_l, sb + 1 * STAGE, 1, tid);
    CP_COMMIT();
    CP_WAIT1();
    __syncthreads();

    const int aRow = warp_m * 32 + (lane & 15);
    const int aCol16 = (lane >> 4) * 16;
    const int bRow = warp_n * 32 + (lane & 7) + ((lane >> 4) << 3);
    const int bCol16 = ((lane >> 3) & 1) * 16;

#pragma unroll 1
    for (int c = 0; c < NCH; c++) {
        const uint32_t st = sb + (c % 3) * STAGE;
        if (c + 2 < NCH)
            issue_stage512<KTOT>(At_h, At_l, Bt_h, Bt_l, sb + ((c + 2) % 3) * STAGE, c + 2, tid);
        CP_COMMIT();

#pragma unroll
        for (int ks = 0; ks < 4; ks++) {
            uint32_t ahf[2][4], alf[2][4], bhf[2][4], blf[2][4];
#pragma unroll
            for (int mt = 0; mt < 2; mt++) {
                uint32_t ad = st + OFF_AH + (uint32_t)(aRow + mt * 16) * ROWB + aCol16 + ks * 32;
                ldsm4(ahf[mt], ad);
                ldsm4(alf[mt], ad + (OFF_AL - OFF_AH));
            }
#pragma unroll
            for (int nh = 0; nh < 2; nh++) {
                uint32_t bd = st + OFF_BH + (uint32_t)(bRow + nh * 16) * ROWB + bCol16 + ks * 32;
                ldsm4(bhf[nh], bd);
                ldsm4(blf[nh], bd + (OFF_BL - OFF_BH));
            }
#pragma unroll
            for (int mt = 0; mt < 2; mt++)
#pragma unroll
                for (int nt = 0; nt < 4; nt++) {
                    const uint32_t* bh2 = &bhf[nt >> 1][(nt & 1) * 2];
                    const uint32_t* bl2 = &blf[nt >> 1][(nt & 1) * 2];
                    mma16816(acc[mt][nt], ahf[mt], bh2);
                    mma16816(acc[mt][nt], ahf[mt], bl2);
                    mma16816(acc[mt][nt], alf[mt], bh2);
                }
        }
        CP_WAIT1();
        __syncthreads();
    }

#pragma unroll
    for (int mt = 0; mt < 2; mt++) {
        const int row0 = by * 128 + warp_m * 32 + mt * 16 + (lane >> 2);
#pragma unroll
        for (int nt = 0; nt < 4; nt++) {
            const int col = bx * 128 + warp_n * 32 + nt * 8 + (lane & 3) * 2;
            const float bv0 = __ldg(bias + col), bv1 = __ldg(bias + col + 1);
#pragma unroll
            for (int half = 0; half < 2; half++) {
                const int row = row0 + half * 8;
                float v0 = acc[mt][nt][half * 2 + 0] + bv0;
                float v1 = acc[mt][nt][half * 2 + 1] + bv1;
                if (GELU_EPI) {
                    v0 = gelu_exact(v0); v1 = gelu_exact(v1);
                    __nv_bfloat16 h0 = __float2bfloat16(v0), h1 = __float2bfloat16(v1);
                    __nv_bfloat16 l0 = __float2bfloat16(v0 - __bfloat162float(h0));
                    __nv_bfloat16 l1 = __float2bfloat16(v1 - __bfloat162float(h1));
                    uint32_t ph = (uint32_t)__bfloat16_as_ushort(h0) | ((uint32_t)__bfloat16_as_ushort(h1) << 16);
                    uint32_t pl = (uint32_t)__bfloat16_as_ushort(l0) | ((uint32_t)__bfloat16_as_ushort(l1) << 16);
                    *(uint32_t*)(Ch + (size_t)row * NOUT + col) = ph;
                    *(uint32_t*)(Cl + (size_t)row * NOUT + col) = pl;
                } else {
                    *(float2*)(Cf + (size_t)row * NOUT + col) = make_float2(v0, v1);
                }
            }
        }
    }
}

// ---------------- skinny scores GEMM (unchanged from R7/R8 pass) ----------------
__global__ void __launch_bounds__(128, 2)
skinny_scores(const __nv_bfloat16* __restrict__ Ah, const __nv_bfloat16* __restrict__ Al,
              const __nv_bfloat16* __restrict__ Bh, const __nv_bfloat16* __restrict__ Bl,
              float* __restrict__ S)
{
    extern __shared__ __align__(128) char smem[];
    const uint32_t sb = smem_u32(smem);
    const int tid = threadIdx.x;
    const int wid = tid >> 5, lane = tid & 31;
    const int row0 = blockIdx.x * 128;
    constexpr int NCH = HDIM / 64;

    const __nv_bfloat16* At_h = Ah + (size_t)row0 * HDIM;
    const __nv_bfloat16* At_l = Al + (size_t)row0 * HDIM;

    float acc[2][4];
#pragma unroll
    for (int i = 0; i < 2; i++)
#pragma unroll
        for (int j = 0; j < 4; j++) acc[i][j] = 0.f;

    auto issue = [&](uint32_t base, int kblk) {
        const size_t kb = (size_t)kblk * 64;
#pragma unroll
        for (int j = 0; j < 8; j++) {
            int idx = tid + j * 128;
            int r = idx >> 3, ch = idx & 7;
            uint32_t so = base + r * SK_ROWB + ch * 16;
            size_t go = (size_t)r * HDIM + kb + ch * 8;
            cpa16(so, At_h + go);
            cpa16(so + SK_OFFAL, At_l + go);
        }
    };

    issue(sb + 0 * SK_STAGE, 0); CP_COMMIT();
    issue(sb + 1 * SK_STAGE, 1); CP_COMMIT();
    CP_WAIT1();
    __syncthreads();

    const int aRowOff = wid * 32 + (lane & 15);
    const int aCol16 = (lane >> 4) * 16;
    const int bn = lane >> 2;
    const int bk0 = (lane & 3) * 2;

#pragma unroll 1
    for (int c = 0; c < NCH; c++) {
        const uint32_t st = sb + (c % 3) * SK_STAGE;
        if (c + 2 < NCH) issue(sb + ((c + 2) % 3) * SK_STAGE, c + 2);
        CP_COMMIT();

#pragma unroll
        for (int ks = 0; ks < 4; ks++) {
            const int kbase = c * 64 + ks * 16;
            uint32_t bh[2], bl[2];
            bh[0] = __ldg((const uint32_t*)(Bh + (size_t)bn * HDIM + kbase + bk0));
            bh[1] = __ldg((const uint32_t*)(Bh + (size_t)bn * HDIM + kbase + bk0 + 8));
            bl[0] = __ldg((const uint32_t*)(Bl + (size_t)bn * HDIM + kbase + bk0));
            bl[1] = __ldg((const uint32_t*)(Bl + (size_t)bn * HDIM + kbase + bk0 + 8));
#pragma unroll
            for (int mt = 0; mt < 2; mt++) {
                uint32_t ahf[4], alf[4];
                uint32_t ad = st + (uint32_t)(aRowOff + mt * 16) * SK_ROWB + aCol16 + ks * 32;
                ldsm4(ahf, ad);
                ldsm4(alf, ad + SK_OFFAL);
                mma16816(acc[mt], ahf, bh);
                mma16816(acc[mt], ahf, bl);
                mma16816(acc[mt], alf, bh);
            }
        }
        CP_WAIT1();
        __syncthreads();
    }

#pragma unroll
    for (int mt = 0; mt < 2; mt++) {
        const int r0 = row0 + wid * 32 + mt * 16 + (lane >> 2);
        const int col = (lane & 3) * 2;
#pragma unroll
        for (int half = 0; half < 2; half++) {
            *(float2*)(S + (size_t)(r0 + half * 8) * EDIM + col) =
                make_float2(acc[mt][half * 2], acc[mt][half * 2 + 1]);
        }
    }
}

// ---------------- routing tail (unchanged from R7/R8 pass) ----------------
__global__ void __launch_bounds__(256)
route_kernel(const float* __restrict__ S, const float* __restrict__ x,
             const float* __restrict__ noise,
             const float* __restrict__ nw, const float* __restrict__ nb,
             const float* __restrict__ temp_p, const float* __restrict__ b2tq,
             float* __restrict__ out_router, float* __restrict__ out_idx, int M)
{
    __shared__ float nws[CDIM];
    __shared__ float b2s[EDIM];
    for (int i = threadIdx.x; i < CDIM; i += blockDim.x) nws[i] = nw[i];
    if (threadIdx.x < EDIM) b2s[threadIdx.x] = b2tq[threadIdx.x];
    __syncthreads();

    const int lane = threadIdx.x & 31;
    const int warp = threadIdx.x >> 5;
    const float temp = *temp_p;
    const float nbv  = *nb;

    for (int t = blockIdx.x * 8 + warp; t < M; t += gridDim.x * 8) {
        const float* xr = x + (size_t)t * CDIM;
        float accg = 0.f;
        for (int j = lane; j < CDIM; j += 32) accg += xr[j] * nws[j];
#pragma unroll
        for (int off = 16; off >= 1; off >>= 1)
            accg += __shfl_xor_sync(0xffffffffu, accg, off);

        float gate = 1.f / (1.f + expf(-(accg + nbv)));

        const float4* sp = (const float4*)(S + (size_t)t * EDIM);
        float4 s0 = sp[0], s1 = sp[1];
        float sc[EDIM] = { s0.x, s0.y, s0.z, s0.w, s1.x, s1.y, s1.z, s1.w };

        float noisy[EDIM];
#pragma unroll
        for (int e = 0; e < EDIM; e++)
            noisy[e] = sc[e] + b2s[e] + temp * noise[(size_t)t * EDIM + e] * gate;

        int i0 = 0; float v0 = noisy[0];
#pragma unroll
        for (int e = 1; e < EDIM; e++)
            if (noisy[e] > v0) { v0 = noisy[e]; i0 = e; }
        int i1 = -1; float v1 = -INFINITY;
#pragma unroll
        for (int e = 0; e < EDIM; e++)
            if (e != i0 && noisy[e] > v1) { v1 = noisy[e]; i1 = e; }

        float inv = 1.f / (temp + 1e-6f);
        float e1 = expf((v1 - v0) * inv);
        float denom = 1.f + e1;
        float p0 = 1.f / denom;
        float p1 = e1 / denom;

        if (lane < EDIM) {
            float pv = (lane == i0) ? p0 : ((lane == i1) ? p1 : 0.f);
            out_router[(size_t)t * EDIM + lane] = pv;
        }
        if (out_idx != nullptr && lane == 0) {
            out_idx[(size_t)t * 2 + 0] = (float)i0;
            out_idx[(size_t)t * 2 + 1] = (float)i1;
        }
    }
}

// ---------------- launch ----------------
extern "C" void kernel_launch(void* const* d_in, const int* in_sizes, int n_in,
                              void* d_out, int out_size)
{
    const float* x     = (const float*)d_in[0];
    const float* noise = (const float*)d_in[1];
    const float* W1    = (const float*)d_in[2];
    const float* b1    = (const float*)d_in[3];
    const float* W2    = (const float*)d_in[4];
    const float* b2    = (const float*)d_in[5];
    const float* tq    = (const float*)d_in[6];
    const float* nw    = (const float*)d_in[7];
    const float* nb    = (const float*)d_in[8];
    const float* temp  = (const float*)d_in[9];

    const int M = in_sizes[0] / CDIM;   // 32768

    __nv_bfloat16 *xh, *xl, *w1h, *w1l, *hh, *hl, *w2tqh, *w2tql;
    float *scores, *b2tqp;
    cudaGetSymbolAddress((void**)&xh,  g_xh);    cudaGetSymbolAddress((void**)&xl,  g_xl);
    cudaGetSymbolAddress((void**)&w1h, g_w1h);   cudaGetSymbolAddress((void**)&w1l, g_w1l);
    cudaGetSymbolAddress((void**)&hh,  g_hh);    cudaGetSymbolAddress((void**)&hl,  g_hl);
    cudaGetSymbolAddress((void**)&w2tqh, g_w2tqh); cudaGetSymbolAddress((void**)&w2tql, g_w2tql);
    cudaGetSymbolAddress((void**)&scores, g_scores); cudaGetSymbolAddress((void**)&b2tqp, g_b2tq);

    cudaFuncSetAttribute(gemm_mma<CDIM, HDIM, 1>, cudaFuncAttributeMaxDynamicSharedMemorySize, SMEM_TOT);
    cudaFuncSetAttribute(skinny_scores, cudaFuncAttributeMaxDynamicSharedMemorySize, SK_SMEM);

    // prep: split x, transpose+split W1, fold W2 into tq
    int n4 = (M * CDIM) / 4;
    split_x_kernel<<<(n4 + 255) / 256, 256>>>(x, xh, xl, n4);
    tsplit_kernel<<<dim3(HDIM / 32, CDIM / 32), dim3(32, 32)>>>(W1, w1h, w1l, CDIM, HDIM);
    w2tq_kernel<<<513, 256>>>(W2, tq, b2, w2tqh, w2tql, b2tqp);

    // GEMM1: h = GELU(x@W1+b1), stored as bf16 split (512 threads, BK=64)
    gemm_mma<CDIM, HDIM, 1><<<dim3(HDIM / 128, M / 128), 512, SMEM_TOT>>>(
        xh, xl, w1h, w1l, b1, nullptr, hh, hl);

    // skinny GEMM: scores = h @ W2tq^T
    skinny_scores<<<M / 128, 128, SK_SMEM>>>(hh, hl, w2tqh, w2tql, scores);

    float* out = (float*)d_out;
    float* out_router = out;
    float* out_idx = nullptr;
    if (out_size >= M * EDIM + M * 2)
        out_idx = out + (size_t)M * EDIM;

    route_kernel<<<M / 8, 256>>>(scores, x, noise, nw, nb, temp, b2tqp,
                                 out_router, out_idx, M);
}

// round 12
// speedup vs baseline: 5.4243x; 1.0436x over previous
#include <cuda_runtime.h>
#include <cuda_bf16.h>
#include <math.h>
#include <stdint.h>

#define MTOT 32768
#define CDIM 1024
#define HDIM 4096
#define EDIM 8
#define NXSL (HDIM / 128)          // 32 hdim slices (GEMM1 bx count)

// ---- GEMM1 tiling: 128x128 CTA tile, BK=64, 16 warps of 32x32, 3 cp.async stages ----
#define ROWB   144                 // 64 bf16 = 128B + 16B pad (ldsm conflict-free)
#define SM_W2  0                   // 4 KB: w2tq slice [128][8] fp32
#define SM_ST  4096                // stages start
#define OFF_AH 0
#define OFF_AL 18432
#define OFF_BH 36864
#define OFF_BL 55296
#define STAGE  73728
#define SMEM_TOT (SM_ST + 3 * STAGE)   // 225280 bytes (<= 227KB cap)

// ---------------- device globals (no runtime allocation allowed) ----------------
__device__ __nv_bfloat16 g_xh[(size_t)MTOT*CDIM], g_xl[(size_t)MTOT*CDIM];   // x split
__device__ __nv_bfloat16 g_w1h[(size_t)HDIM*CDIM], g_w1l[(size_t)HDIM*CDIM]; // W1^T split [N][K]
__device__ float g_w2tqf[(size_t)HDIM*EDIM];                                  // (W2@tq^T) fp32 [H][E]
__device__ float g_b2tq[EDIM];
__device__ float g_spart[(size_t)NXSL*MTOT*EDIM];                             // partial scores per hdim-slice
__device__ float g_scores[(size_t)MTOT*EDIM];

// ---------------- PTX helpers (base sm_100-compatible PTX only) ----------------
__device__ __forceinline__ uint32_t smem_u32(const void* p) {
    uint32_t a;
    asm("{ .reg .u64 t; cvta.to.shared.u64 t, %1; cvt.u32.u64 %0, t; }" : "=r"(a) : "l"(p));
    return a;
}
__device__ __forceinline__ void cpa16(uint32_t d, const void* s) {
    asm volatile("cp.async.cg.shared.global [%0], [%1], 16;" :: "r"(d), "l"(s));
}
#define CP_COMMIT() asm volatile("cp.async.commit_group;" ::: "memory")
#define CP_WAIT1()  asm volatile("cp.async.wait_group 1;" ::: "memory")

__device__ __forceinline__ void ldsm4(uint32_t* r, uint32_t a) {
    asm volatile("ldmatrix.sync.aligned.m8n8.x4.shared.b16 {%0,%1,%2,%3}, [%4];"
        : "=r"(r[0]), "=r"(r[1]), "=r"(r[2]), "=r"(r[3]) : "r"(a));
}
__device__ __forceinline__ void mma16816(float* c, const uint32_t* a, const uint32_t* b) {
    asm volatile("mma.sync.aligned.m16n8k16.row.col.f32.bf16.bf16.f32 "
        "{%0,%1,%2,%3}, {%4,%5,%6,%7}, {%8,%9}, {%0,%1,%2,%3};"
        : "+f"(c[0]), "+f"(c[1]), "+f"(c[2]), "+f"(c[3])
        : "r"(a[0]), "r"(a[1]), "r"(a[2]), "r"(a[3]), "r"(b[0]), "r"(b[1]));
}

__device__ __forceinline__ float gelu_exact(float v) {
    return 0.5f * v * (1.0f + erff(v * 0.70710678118654752440f));
}

// ---------------- prep kernels ----------------
__global__ void __launch_bounds__(256)
split_x_kernel(const float* __restrict__ in, __nv_bfloat16* __restrict__ hi,
               __nv_bfloat16* __restrict__ lo, int n4)
{
    int i = blockIdx.x * blockDim.x + threadIdx.x;
    if (i >= n4) return;
    float4 v = ((const float4*)in)[i];
    __nv_bfloat16 h0 = __float2bfloat16(v.x), h1 = __float2bfloat16(v.y);
    __nv_bfloat16 h2 = __float2bfloat16(v.z), h3 = __float2bfloat16(v.w);
    __nv_bfloat16 l0 = __float2bfloat16(v.x - __bfloat162float(h0));
    __nv_bfloat16 l1 = __float2bfloat16(v.y - __bfloat162float(h1));
    __nv_bfloat16 l2 = __float2bfloat16(v.z - __bfloat162float(h2));
    __nv_bfloat16 l3 = __float2bfloat16(v.w - __bfloat162float(h3));
    uint2 hh, ll;
    hh.x = (uint32_t)__bfloat16_as_ushort(h0) | ((uint32_t)__bfloat16_as_ushort(h1) << 16);
    hh.y = (uint32_t)__bfloat16_as_ushort(h2) | ((uint32_t)__bfloat16_as_ushort(h3) << 16);
    ll.x = (uint32_t)__bfloat16_as_ushort(l0) | ((uint32_t)__bfloat16_as_ushort(l1) << 16);
    ll.y = (uint32_t)__bfloat16_as_ushort(l2) | ((uint32_t)__bfloat16_as_ushort(l3) << 16);
    ((uint2*)hi)[i] = hh;
    ((uint2*)lo)[i] = ll;
}

// W1 [K][N] row-major -> T [N][K] bf16 hi/lo
__global__ void __launch_bounds__(1024)
tsplit_kernel(const float* __restrict__ W, __nv_bfloat16* __restrict__ Th,
              __nv_bfloat16* __restrict__ Tl, int K, int N)
{
    __shared__ float t[32][33];
    int n0 = blockIdx.x * 32, k0 = blockIdx.y * 32;
    t[threadIdx.y][threadIdx.x] = W[(size_t)(k0 + threadIdx.y) * N + n0 + threadIdx.x];
    __syncthreads();
    float v = t[threadIdx.x][threadIdx.y];
    int n = n0 + threadIdx.y, k = k0 + threadIdx.x;
    __nv_bfloat16 h = __float2bfloat16(v);
    Th[(size_t)n * K + k] = h;
    Tl[(size_t)n * K + k] = __float2bfloat16(v - __bfloat162float(h));
}

// W2tq[k][e] = sum_c W2[k][c] * tq[e][c]  (fp32), and b2tq[e] = sum_c b2[c]*tq[e][c]
__global__ void __launch_bounds__(256)
w2tq_kernel(const float* __restrict__ W2, const float* __restrict__ tq,
            const float* __restrict__ b2,
            float* __restrict__ Wf, float* __restrict__ b2tq)
{
    __shared__ float tqs[EDIM][CDIM];   // 32 KB
    for (int i = threadIdx.x; i < EDIM * CDIM; i += blockDim.x)
        ((float*)tqs)[i] = tq[i];
    __syncthreads();

    const int lane = threadIdx.x & 31;
    const int warp = threadIdx.x >> 5;

    if (blockIdx.x < 512) {
        const int k = blockIdx.x * 8 + warp;
        const float* wr = W2 + (size_t)k * CDIM;
        float acc[EDIM];
#pragma unroll
        for (int e = 0; e < EDIM; e++) acc[e] = 0.f;
        for (int c = lane; c < CDIM; c += 32) {
            float wv = wr[c];
#pragma unroll
            for (int e = 0; e < EDIM; e++) acc[e] += wv * tqs[e][c];
        }
#pragma unroll
        for (int off = 16; off >= 1; off >>= 1)
#pragma unroll
            for (int e = 0; e < EDIM; e++)
                acc[e] += __shfl_xor_sync(0xffffffffu, acc[e], off);
        if (lane < EDIM) {
            float v = 0.f;
#pragma unroll
            for (int e = 0; e < EDIM; e++) if (lane == e) v = acc[e];
            Wf[(size_t)k * EDIM + lane] = v;
        }
    } else {
        if (warp < EDIM) {
            float a = 0.f;
            for (int c = lane; c < CDIM; c += 32) a += b2[c] * tqs[warp][c];
#pragma unroll
            for (int off = 16; off >= 1; off >>= 1)
                a += __shfl_xor_sync(0xffffffffu, a, off);
            if (lane == 0) b2tq[warp] = a;
        }
    }
}

// ---------------- GEMM1 stage loader (512 threads, BK=64) ----------------
__device__ __forceinline__ void issue_stage512(
    const __nv_bfloat16* __restrict__ Ah, const __nv_bfloat16* __restrict__ Al,
    const __nv_bfloat16* __restrict__ Bh, const __nv_bfloat16* __restrict__ Bl,
    uint32_t stage_base, int kblk, int tid)
{
    const size_t kb = (size_t)kblk * 64;
#pragma unroll
    for (int j = 0; j < 2; j++) {
        int idx = tid + j * 512;
        int r = idx >> 3, ch = idx & 7;
        uint32_t so = stage_base + r * ROWB + ch * 16;
        size_t go = (size_t)r * CDIM + kb + ch * 8;
        cpa16(so + OFF_AH, Ah + go);
        cpa16(so + OFF_AL, Al + go);
        cpa16(so + OFF_BH, Bh + go);
        cpa16(so + OFF_BL, Bl + go);
    }
}

// ---------------- fused GEMM1 + scores partial ----------------
// h = GELU(x@W1^T + b1) held in registers; partial scores = h_tile @ w2tq_slice
// accumulated to g_spart[bx][row][e]. h never touches global memory.
__global__ void __launch_bounds__(512, 1)
gemm_fused(const __nv_bfloat16* __restrict__ Ah, const __nv_bfloat16* __restrict__ Al,
           const __nv_bfloat16* __restrict__ Bh, const __nv_bfloat16* __restrict__ Bl,
           const float* __restrict__ bias, const float* __restrict__ w2tqf,
           float* __restrict__ spart)
{
    extern __shared__ __align__(128) char smem[];
    const uint32_t sb = smem_u32(smem) + SM_ST;
    float* w2s = (float*)(smem + SM_W2);        // [128][8]
    const int tid = threadIdx.x;
    const int wid = tid >> 5, lane = tid & 31;
    const int warp_m = wid >> 2, warp_n = wid & 3;   // 4 x 4 warp grid, 32x32 per warp
    const int bx = blockIdx.x, by = blockIdx.y;
    constexpr int NCH = CDIM / 64;

    const __nv_bfloat16* At_h = Ah + (size_t)(by * 128) * CDIM;
    const __nv_bfloat16* At_l = Al + (size_t)(by * 128) * CDIM;
    const __nv_bfloat16* Bt_h = Bh + (size_t)(bx * 128) * CDIM;
    const __nv_bfloat16* Bt_l = Bl + (size_t)(bx * 128) * CDIM;

    // load this CTA's w2tq slice (128 cols x 8 experts, fp32)
    {
        const float4* src = (const float4*)(w2tqf + (size_t)(bx * 128) * EDIM);
        float4* dst = (float4*)w2s;
        for (int i = tid; i < 128 * EDIM / 4; i += 512) dst[i] = src[i];
    }

    float acc[2][4][4];
#pragma unroll
    for (int i = 0; i < 2; i++)
#pragma unroll
        for (int j = 0; j < 4; j++)
#pragma unroll
            for (int k = 0; k < 4; k++) acc[i][j][k] = 0.f;

    issue_stage512(At_h, At_l, Bt_h, Bt_l, sb + 0 * STAGE, 0, tid);
    CP_COMMIT();
    issue_stage512(At_h, At_l, Bt_h, Bt_l, sb + 1 * STAGE, 1, tid);
    CP_COMMIT();
    CP_WAIT1();
    __syncthreads();

    const int aRow = warp_m * 32 + (lane & 15);
    const int aCol16 = (lane >> 4) * 16;
    const int bRow = warp_n * 32 + (lane & 7) + ((lane >> 4) << 3);
    const int bCol16 = ((lane >> 3) & 1) * 16;

#pragma unroll 1
    for (int c = 0; c < NCH; c++) {
        const uint32_t st = sb + (c % 3) * STAGE;
        if (c + 2 < NCH)
            issue_stage512(At_h, At_l, Bt_h, Bt_l, sb + ((c + 2) % 3) * STAGE, c + 2, tid);
        CP_COMMIT();

#pragma unroll
        for (int ks = 0; ks < 4; ks++) {
            uint32_t ahf[2][4], alf[2][4], bhf[2][4], blf[2][4];
#pragma unroll
            for (int mt = 0; mt < 2; mt++) {
                uint32_t ad = st + OFF_AH + (uint32_t)(aRow + mt * 16) * ROWB + aCol16 + ks * 32;
                ldsm4(ahf[mt], ad);
                ldsm4(alf[mt], ad + (OFF_AL - OFF_AH));
            }
#pragma unroll
            for (int nh = 0; nh < 2; nh++) {
                uint32_t bd = st + OFF_BH + (uint32_t)(bRow + nh * 16) * ROWB + bCol16 + ks * 32;
                ldsm4(bhf[nh], bd);
                ldsm4(blf[nh], bd + (OFF_BL - OFF_BH));
            }
#pragma unroll
            for (int mt = 0; mt < 2; mt++)
#pragma unroll
                for (int nt = 0; nt < 4; nt++) {
                    const uint32_t* bh2 = &bhf[nt >> 1][(nt & 1) * 2];
                    const uint32_t* bl2 = &blf[nt >> 1][(nt & 1) * 2];
                    mma16816(acc[mt][nt], ahf[mt], bh2);
                    mma16816(acc[mt][nt], ahf[mt], bl2);
                    mma16816(acc[mt][nt], alf[mt], bh2);
                }
        }
        CP_WAIT1();
        __syncthreads();
    }

    // ---- fused epilogue: gelu + partial scores, no h stores ----
    float p[4][EDIM];
#pragma unroll
    for (int r = 0; r < 4; r++)
#pragma unroll
        for (int e = 0; e < EDIM; e++) p[r][e] = 0.f;

#pragma unroll
    for (int mt = 0; mt < 2; mt++)
#pragma unroll
        for (int nt = 0; nt < 4; nt++) {
            const int col_local = warp_n * 32 + nt * 8 + (lane & 3) * 2;
            const int col = bx * 128 + col_local;
            const float bv0 = __ldg(bias + col), bv1 = __ldg(bias + col + 1);
            const float* w0 = w2s + col_local * EDIM;
            const float* w1 = w2s + (col_local + 1) * EDIM;
#pragma unroll
            for (int half = 0; half < 2; half++) {
                const int ri = mt * 2 + half;
                float v0 = gelu_exact(acc[mt][nt][half * 2 + 0] + bv0);
                float v1 = gelu_exact(acc[mt][nt][half * 2 + 1] + bv1);
#pragma unroll
                for (int e = 0; e < EDIM; e++)
                    p[ri][e] += v0 * w0[e] + v1 * w1[e];
            }
        }

    // reduce across the 4 lanes of each quad (they cover disjoint cols of same rows)
#pragma unroll
    for (int off = 1; off <= 2; off <<= 1)
#pragma unroll
        for (int r = 0; r < 4; r++)
#pragma unroll
            for (int e = 0; e < EDIM; e++)
                p[r][e] += __shfl_xor_sync(0xffffffffu, p[r][e], off);

    // cross-warp_n reduction through (now free) stage smem: sp[4][128][8]
    float* sp = (float*)(smem + SM_ST);
    __syncthreads();   // all mainloop smem reads complete; safe to reuse
    if ((lane & 3) == 0) {
#pragma unroll
        for (int ri = 0; ri < 4; ri++) {
            const int mt = ri >> 1, half = ri & 1;
            const int row_local = warp_m * 32 + mt * 16 + (lane >> 2) + half * 8;
#pragma unroll
            for (int e = 0; e < EDIM; e++)
                sp[(warp_n * 128 + row_local) * EDIM + e] = p[ri][e];
        }
    }
    __syncthreads();

    // final: sum 4 warp_n slices, write partial to g_spart[bx]
    for (int idx = tid; idx < 128 * EDIM; idx += 512) {
        float s = sp[idx] + sp[128 * EDIM + idx] + sp[256 * EDIM + idx] + sp[384 * EDIM + idx];
        spart[((size_t)bx * MTOT + by * 128) * EDIM + idx] = s;
    }
}

// ---------------- deterministic reduce over hdim slices ----------------
__global__ void __launch_bounds__(256)
reduce_scores(const float* __restrict__ spart, float* __restrict__ S, int n)
{
    int idx = blockIdx.x * blockDim.x + threadIdx.x;
    if (idx >= n) return;
    float s = 0.f;
#pragma unroll
    for (int b = 0; b < NXSL; b++)
        s += spart[(size_t)b * n + idx];
    S[idx] = s;
}

// ---------------- routing tail (unchanged from R10 pass) ----------------
__global__ void __launch_bounds__(256)
route_kernel(const float* __restrict__ S, const float* __restrict__ x,
             const float* __restrict__ noise,
             const float* __restrict__ nw, const float* __restrict__ nb,
             const float* __restrict__ temp_p, const float* __restrict__ b2tq,
             float* __restrict__ out_router, float* __restrict__ out_idx, int M)
{
    __shared__ float nws[CDIM];
    __shared__ float b2s[EDIM];
    for (int i = threadIdx.x; i < CDIM; i += blockDim.x) nws[i] = nw[i];
    if (threadIdx.x < EDIM) b2s[threadIdx.x] = b2tq[threadIdx.x];
    __syncthreads();

    const int lane = threadIdx.x & 31;
    const int warp = threadIdx.x >> 5;
    const float temp = *temp_p;
    const float nbv  = *nb;

    for (int t = blockIdx.x * 8 + warp; t < M; t += gridDim.x * 8) {
        const float* xr = x + (size_t)t * CDIM;
        float accg = 0.f;
        for (int j = lane; j < CDIM; j += 32) accg += xr[j] * nws[j];
#pragma unroll
        for (int off = 16; off >= 1; off >>= 1)
            accg += __shfl_xor_sync(0xffffffffu, accg, off);

        float gate = 1.f / (1.f + expf(-(accg + nbv)));

        const float4* sp = (const float4*)(S + (size_t)t * EDIM);
        float4 s0 = sp[0], s1 = sp[1];
        float sc[EDIM] = { s0.x, s0.y, s0.z, s0.w, s1.x, s1.y, s1.z, s1.w };

        float noisy[EDIM];
#pragma unroll
        for (int e = 0; e < EDIM; e++)
            noisy[e] = sc[e] + b2s[e] + temp * noise[(size_t)t * EDIM + e] * gate;

        int i0 = 0; float v0 = noisy[0];
#pragma unroll
        for (int e = 1; e < EDIM; e++)
            if (noisy[e] > v0) { v0 = noisy[e]; i0 = e; }
        int i1 = -1; float v1 = -INFINITY;
#pragma unroll
        for (int e = 0; e < EDIM; e++)
            if (e != i0 && noisy[e] > v1) { v1 = noisy[e]; i1 = e; }

        float inv = 1.f / (temp + 1e-6f);
        float e1 = expf((v1 - v0) * inv);
        float denom = 1.f + e1;
        float p0 = 1.f / denom;
        float p1 = e1 / denom;

        if (lane < EDIM) {
            float pv = (lane == i0) ? p0 : ((lane == i1) ? p1 : 0.f);
            out_router[(size_t)t * EDIM + lane] = pv;
        }
        if (out_idx != nullptr && lane == 0) {
            out_idx[(size_t)t * 2 + 0] = (float)i0;
            out_idx[(size_t)t * 2 + 1] = (float)i1;
        }
    }
}

// ---------------- launch ----------------
extern "C" void kernel_launch(void* const* d_in, const int* in_sizes, int n_in,
                              void* d_out, int out_size)
{
    const float* x     = (const float*)d_in[0];
    const float* noise = (const float*)d_in[1];
    const float* W1    = (const float*)d_in[2];
    const float* b1    = (const float*)d_in[3];
    const float* W2    = (const float*)d_in[4];
    const float* b2    = (const float*)d_in[5];
    const float* tq    = (const float*)d_in[6];
    const float* nw    = (const float*)d_in[7];
    const float* nb    = (const float*)d_in[8];
    const float* temp  = (const float*)d_in[9];

    const int M = in_sizes[0] / CDIM;   // 32768

    __nv_bfloat16 *xh, *xl, *w1h, *w1l;
    float *w2tqf, *scores, *spart, *b2tqp;
    cudaGetSymbolAddress((void**)&xh,  g_xh);    cudaGetSymbolAddress((void**)&xl,  g_xl);
    cudaGetSymbolAddress((void**)&w1h, g_w1h);   cudaGetSymbolAddress((void**)&w1l, g_w1l);
    cudaGetSymbolAddress((void**)&w2tqf, g_w2tqf);
    cudaGetSymbolAddress((void**)&scores, g_scores);
    cudaGetSymbolAddress((void**)&spart, g_spart);
    cudaGetSymbolAddress((void**)&b2tqp, g_b2tq);

    cudaFuncSetAttribute(gemm_fused, cudaFuncAttributeMaxDynamicSharedMemorySize, SMEM_TOT);

    // prep: split x, transpose+split W1, fold W2 into tq (fp32)
    int n4 = (M * CDIM) / 4;
    split_x_kernel<<<(n4 + 255) / 256, 256>>>(x, xh, xl, n4);
    tsplit_kernel<<<dim3(HDIM / 32, CDIM / 32), dim3(32, 32)>>>(W1, w1h, w1l, CDIM, HDIM);
    w2tq_kernel<<<513, 256>>>(W2, tq, b2, w2tqf, b2tqp);

    // fused GEMM1 + scores partials (h never hits global memory)
    gemm_fused<<<dim3(HDIM / 128, M / 128), 512, SMEM_TOT>>>(
        xh, xl, w1h, w1l, b1, w2tqf, spart);

    // deterministic reduction over the 32 hdim slices
    reduce_scores<<<(M * EDIM + 255) / 256, 256>>>(spart, scores, M * EDIM);

    float* out = (float*)d_out;
    float* out_router = out;
    float* out_idx = nullptr;
    if (out_size >= M * EDIM + M * 2)
        out_idx = out + (size_t)M * EDIM;

    route_kernel<<<M / 8, 256>>>(scores, x, noise, nw, nb, temp, b2tqp,
                                 out_router, out_idx, M);
}